// round 1
// baseline (speedup 1.0000x reference)
#include <cuda_runtime.h>
#include <math.h>

#define SQ   4096
#define EM   2048
#define NH   16
#define HD   128
#define QKVC (3*EM)

// Scratch (allocation-free rule: device globals)
__device__ float g_qkv[(size_t)SQ * QKVC];   // [S, 3E]  (q | k | v)
__device__ float g_ctx[(size_t)SQ * EM];     // [S, E]   attention output

// =====================================================================
// GEMM: C[M,N] = A[M,K] @ B[N,K]^T + bias[N]   (both K-contiguous, "TN")
// 128x128 block tile, K-tile 16, 256 threads, 8x8 per thread, double buffer
// =====================================================================
#define GBM 128
#define GBN 128
#define GBK 16
#define GSTR 132   // padded row stride (floats) in smem

__global__ __launch_bounds__(256, 2)
void gemm_tn(const float* __restrict__ A, const float* __restrict__ B,
             const float* __restrict__ bias, float* __restrict__ C,
             int M, int N, int K)
{
    __shared__ __align__(16) float As[2][GBK][GSTR];
    __shared__ __align__(16) float Bs[2][GBK][GSTR];

    const int tid = threadIdx.x;
    const int bm = blockIdx.y * GBM;
    const int bn = blockIdx.x * GBN;

    // global-load mapping: 512 float4 per operand tile, 2 per thread
    const int r0 = tid >> 2;          // 0..63
    const int r1 = r0 + 64;           // 64..127
    const int kc = (tid & 3) << 2;    // 0,4,8,12

    const float* Ap0 = A + (size_t)(bm + r0) * K + kc;
    const float* Ap1 = A + (size_t)(bm + r1) * K + kc;
    const float* Bp0 = B + (size_t)(bn + r0) * K + kc;
    const float* Bp1 = B + (size_t)(bn + r1) * K + kc;

    const int ty = tid >> 4;   // 0..15
    const int tx = tid & 15;   // 0..15

    float acc[8][8];
    #pragma unroll
    for (int i = 0; i < 8; i++)
        #pragma unroll
        for (int j = 0; j < 8; j++) acc[i][j] = 0.0f;

    const int nk = K / GBK;

    float4 pa0 = *(const float4*)(Ap0);
    float4 pa1 = *(const float4*)(Ap1);
    float4 pb0 = *(const float4*)(Bp0);
    float4 pb1 = *(const float4*)(Bp1);

    // stage tile 0
    As[0][kc+0][r0]=pa0.x; As[0][kc+1][r0]=pa0.y; As[0][kc+2][r0]=pa0.z; As[0][kc+3][r0]=pa0.w;
    As[0][kc+0][r1]=pa1.x; As[0][kc+1][r1]=pa1.y; As[0][kc+2][r1]=pa1.z; As[0][kc+3][r1]=pa1.w;
    Bs[0][kc+0][r0]=pb0.x; Bs[0][kc+1][r0]=pb0.y; Bs[0][kc+2][r0]=pb0.z; Bs[0][kc+3][r0]=pb0.w;
    Bs[0][kc+0][r1]=pb1.x; Bs[0][kc+1][r1]=pb1.y; Bs[0][kc+2][r1]=pb1.z; Bs[0][kc+3][r1]=pb1.w;
    __syncthreads();

    for (int kt = 0; kt < nk; kt++) {
        const int buf = kt & 1;
        const bool more = (kt + 1) < nk;
        if (more) {
            const size_t off = (size_t)(kt + 1) * GBK;
            pa0 = *(const float4*)(Ap0 + off);
            pa1 = *(const float4*)(Ap1 + off);
            pb0 = *(const float4*)(Bp0 + off);
            pb1 = *(const float4*)(Bp1 + off);
        }
        #pragma unroll
        for (int kk = 0; kk < GBK; kk++) {
            float4 a0 = *(const float4*)&As[buf][kk][ty*8];
            float4 a1 = *(const float4*)&As[buf][kk][ty*8+4];
            float4 b0 = *(const float4*)&Bs[buf][kk][tx*8];
            float4 b1 = *(const float4*)&Bs[buf][kk][tx*8+4];
            float a[8] = {a0.x,a0.y,a0.z,a0.w,a1.x,a1.y,a1.z,a1.w};
            float b[8] = {b0.x,b0.y,b0.z,b0.w,b1.x,b1.y,b1.z,b1.w};
            #pragma unroll
            for (int i = 0; i < 8; i++)
                #pragma unroll
                for (int j = 0; j < 8; j++)
                    acc[i][j] = fmaf(a[i], b[j], acc[i][j]);
        }
        if (more) {
            const int nb = buf ^ 1;
            As[nb][kc+0][r0]=pa0.x; As[nb][kc+1][r0]=pa0.y; As[nb][kc+2][r0]=pa0.z; As[nb][kc+3][r0]=pa0.w;
            As[nb][kc+0][r1]=pa1.x; As[nb][kc+1][r1]=pa1.y; As[nb][kc+2][r1]=pa1.z; As[nb][kc+3][r1]=pa1.w;
            Bs[nb][kc+0][r0]=pb0.x; Bs[nb][kc+1][r0]=pb0.y; Bs[nb][kc+2][r0]=pb0.z; Bs[nb][kc+3][r0]=pb0.w;
            Bs[nb][kc+0][r1]=pb1.x; Bs[nb][kc+1][r1]=pb1.y; Bs[nb][kc+2][r1]=pb1.z; Bs[nb][kc+3][r1]=pb1.w;
        }
        __syncthreads();
    }

    float bv[8];
    #pragma unroll
    for (int j = 0; j < 8; j++) bv[j] = bias[bn + tx*8 + j];

    #pragma unroll
    for (int i = 0; i < 8; i++) {
        float* Cp = C + (size_t)(bm + ty*8 + i) * N + bn + tx*8;
        float4 v0 = make_float4(acc[i][0]+bv[0], acc[i][1]+bv[1], acc[i][2]+bv[2], acc[i][3]+bv[3]);
        float4 v1 = make_float4(acc[i][4]+bv[4], acc[i][5]+bv[5], acc[i][6]+bv[6], acc[i][7]+bv[7]);
        *(float4*)(Cp)     = v0;
        *(float4*)(Cp + 4) = v1;
    }
}

// =====================================================================
// Flash attention (causal, fp32, online softmax)
// Br=Bc=64, D=128, 256 threads; thread grid 16x16:
//   S rows m = ty+16i (i<4), S cols n = tx+16j (j<4)
//   O rows same, O cols c = tx*8+j (j<8)
// =====================================================================
#define BR 64
#define BC 64
#define FSTR 132          // Q/K/V smem row stride
#define PSTR 65           // P (k-major) row stride
#define FLASH_SMEM (3 * BR * FSTR * (int)sizeof(float))   // 101376 B

__device__ __forceinline__ float redmax16(float v) {
    v = fmaxf(v, __shfl_xor_sync(0xffffffffu, v, 1));
    v = fmaxf(v, __shfl_xor_sync(0xffffffffu, v, 2));
    v = fmaxf(v, __shfl_xor_sync(0xffffffffu, v, 4));
    v = fmaxf(v, __shfl_xor_sync(0xffffffffu, v, 8));
    return v;
}
__device__ __forceinline__ float redsum16(float v) {
    v += __shfl_xor_sync(0xffffffffu, v, 1);
    v += __shfl_xor_sync(0xffffffffu, v, 2);
    v += __shfl_xor_sync(0xffffffffu, v, 4);
    v += __shfl_xor_sync(0xffffffffu, v, 8);
    return v;
}

__global__ __launch_bounds__(256, 2)
void flash_attn(const float* __restrict__ qkv, float* __restrict__ ctx)
{
    extern __shared__ __align__(16) float sm[];
    float* Qs = sm;                   // [64][132]
    float* Ks = sm + BR * FSTR;       // [64][132]; reused as Ps[64][65] after QK
    float* Vs = sm + 2 * BR * FSTR;   // [64][132]
    float* Ps = Ks;

    const int tid = threadIdx.x;
    const int tx = tid & 15;
    const int ty = tid >> 4;
    const int h  = blockIdx.y;
    const int qb = blockIdx.x;

    const float scale = 0.08838834764831845f;  // 1/sqrt(128)

    // load Q tile [64][128]
    const float* qbase = qkv + (size_t)(qb * BR) * QKVC + h * HD;
    #pragma unroll
    for (int l = 0; l < 8; l++) {
        int idx = tid + l * 256;
        int r = idx >> 5;
        int c = (idx & 31) << 2;
        *(float4*)(Qs + r * FSTR + c) = *(const float4*)(qbase + (size_t)r * QKVC + c);
    }

    float m_i[4], l_i[4], o[4][8];
    #pragma unroll
    for (int i = 0; i < 4; i++) {
        m_i[i] = -1e30f; l_i[i] = 0.0f;
        #pragma unroll
        for (int j = 0; j < 8; j++) o[i][j] = 0.0f;
    }

    for (int kb = 0; kb <= qb; kb++) {
        __syncthreads();   // previous PV done (and Q staged on first iter)
        const float* kp = qkv + (size_t)(kb * BC) * QKVC + EM + h * HD;
        const float* vp = kp + EM;
        #pragma unroll
        for (int l = 0; l < 8; l++) {
            int idx = tid + l * 256;
            int r = idx >> 5;
            int c = (idx & 31) << 2;
            *(float4*)(Ks + r * FSTR + c) = *(const float4*)(kp + (size_t)r * QKVC + c);
            *(float4*)(Vs + r * FSTR + c) = *(const float4*)(vp + (size_t)r * QKVC + c);
        }
        __syncthreads();

        // S = Q @ K^T
        float s[4][4];
        #pragma unroll
        for (int i = 0; i < 4; i++)
            #pragma unroll
            for (int j = 0; j < 4; j++) s[i][j] = 0.0f;

        #pragma unroll
        for (int d = 0; d < HD; d += 4) {
            float4 aq[4], bk[4];
            #pragma unroll
            for (int i = 0; i < 4; i++) aq[i] = *(const float4*)(Qs + (ty + 16*i) * FSTR + d);
            #pragma unroll
            for (int j = 0; j < 4; j++) bk[j] = *(const float4*)(Ks + (tx + 16*j) * FSTR + d);
            #pragma unroll
            for (int i = 0; i < 4; i++)
                #pragma unroll
                for (int j = 0; j < 4; j++) {
                    s[i][j] = fmaf(aq[i].x, bk[j].x, s[i][j]);
                    s[i][j] = fmaf(aq[i].y, bk[j].y, s[i][j]);
                    s[i][j] = fmaf(aq[i].z, bk[j].z, s[i][j]);
                    s[i][j] = fmaf(aq[i].w, bk[j].w, s[i][j]);
                }
        }

        // online softmax
        const bool diag = (kb == qb);
        #pragma unroll
        for (int i = 0; i < 4; i++) {
            const int row = ty + 16*i;
            float mloc = -1e30f;
            #pragma unroll
            for (int j = 0; j < 4; j++) {
                float v = s[i][j] * scale;
                if (diag && (tx + 16*j) > row) v = -1e30f;
                s[i][j] = v;
                mloc = fmaxf(mloc, v);
            }
            mloc = redmax16(mloc);
            const float mnew = fmaxf(m_i[i], mloc);
            float rsum = 0.0f;
            #pragma unroll
            for (int j = 0; j < 4; j++) {
                float p = __expf(s[i][j] - mnew);
                s[i][j] = p;
                rsum += p;
            }
            rsum = redsum16(rsum);
            const float f = __expf(m_i[i] - mnew);
            l_i[i] = l_i[i] * f + rsum;
            m_i[i] = mnew;
            #pragma unroll
            for (int j = 0; j < 8; j++) o[i][j] *= f;
        }

        __syncthreads();   // all QK reads of Ks done before Ps overwrites it
        #pragma unroll
        for (int j = 0; j < 4; j++)
            #pragma unroll
            for (int i = 0; i < 4; i++)
                Ps[(tx + 16*j) * PSTR + (ty + 16*i)] = s[i][j];
        __syncthreads();

        // O += P @ V
        #pragma unroll 4
        for (int n = 0; n < BC; n++) {
            float a[4];
            #pragma unroll
            for (int i = 0; i < 4; i++) a[i] = Ps[n * PSTR + ty + 16*i];
            float4 b0 = *(const float4*)(Vs + n * FSTR + tx*8);
            float4 b1 = *(const float4*)(Vs + n * FSTR + tx*8 + 4);
            float b[8] = {b0.x,b0.y,b0.z,b0.w,b1.x,b1.y,b1.z,b1.w};
            #pragma unroll
            for (int i = 0; i < 4; i++)
                #pragma unroll
                for (int j = 0; j < 8; j++)
                    o[i][j] = fmaf(a[i], b[j], o[i][j]);
        }
    }

    // epilogue: O /= l, write [S, E] with heads concatenated
    #pragma unroll
    for (int i = 0; i < 4; i++) {
        const int row = qb * BR + ty + 16*i;
        const float inv = 1.0f / l_i[i];
        float* op = ctx + (size_t)row * EM + h * HD + tx*8;
        float4 v0 = make_float4(o[i][0]*inv, o[i][1]*inv, o[i][2]*inv, o[i][3]*inv);
        float4 v1 = make_float4(o[i][4]*inv, o[i][5]*inv, o[i][6]*inv, o[i][7]*inv);
        *(float4*)(op)     = v0;
        *(float4*)(op + 4) = v1;
    }
}

// =====================================================================
extern "C" void kernel_launch(void* const* d_in, const int* in_sizes, int n_in,
                              void* d_out, int out_size)
{
    (void)in_sizes; (void)n_in; (void)out_size;
    const float* hs   = (const float*)d_in[0];
    const float* wqkv = (const float*)d_in[1];
    const float* bqkv = (const float*)d_in[2];
    const float* wo   = (const float*)d_in[3];
    const float* bo   = (const float*)d_in[4];
    float* out = (float*)d_out;

    float *qkv, *ctx;
    cudaGetSymbolAddress((void**)&qkv, g_qkv);
    cudaGetSymbolAddress((void**)&ctx, g_ctx);

    cudaFuncSetAttribute(flash_attn, cudaFuncAttributeMaxDynamicSharedMemorySize, FLASH_SMEM);

    // 1) QKV projection: [S,3E] = hs[S,E] @ Wqkv[3E,E]^T + bqkv
    dim3 g1(QKVC / GBN, SQ / GBM);
    gemm_tn<<<g1, 256>>>(hs, wqkv, bqkv, qkv, SQ, QKVC, EM);

    // 2) causal flash attention -> ctx[S,E]
    dim3 g2(SQ / BR, NH);
    flash_attn<<<g2, 256, FLASH_SMEM>>>(qkv, ctx);

    // 3) output projection: out[S,E] = ctx @ Wo[E,E]^T + bo
    dim3 g3(EM / GBN, SQ / GBM);
    gemm_tn<<<g3, 256>>>(ctx, wo, bo, out, SQ, EM, EM);
}

// round 3
// speedup vs baseline: 1.3439x; 1.3439x over previous
#include <cuda_runtime.h>
#include <cuda_bf16.h>
#include <math.h>
#include <cstdint>

#define SQ   4096
#define EM   2048
#define NH   16
#define HD   128
#define QKVC (3*EM)

// ---------------------------------------------------------------------
// Scratch (allocation-free rule: device globals)
// ---------------------------------------------------------------------
__device__ float g_qkv[(size_t)SQ * QKVC];            // [S, 3E] fp32 (q|k|v)
__device__ float g_ctx[(size_t)SQ * EM];              // [S, E]  fp32 attention out
__device__ __nv_bfloat16 g_ah[(size_t)SQ * EM];       // A hi split (hs or ctx)
__device__ __nv_bfloat16 g_al[(size_t)SQ * EM];       // A lo split
__device__ __nv_bfloat16 g_bh[(size_t)QKVC * EM];     // W hi split (Wqkv or Wo)
__device__ __nv_bfloat16 g_bl[(size_t)QKVC * EM];     // W lo split

// ---------------------------------------------------------------------
// Portable PTX helpers (sm_80-class: valid under compute_103 target)
// ---------------------------------------------------------------------
__device__ __forceinline__ uint32_t smem_u32(const void* p) {
    uint32_t a;
    asm("{ .reg .u64 t; cvta.to.shared.u64 t, %1; cvt.u32.u64 %0, t; }" : "=r"(a) : "l"(p));
    return a;
}
__device__ __forceinline__ void cp_async16(uint32_t saddr, const void* gaddr) {
    asm volatile("cp.async.cg.shared.global [%0], [%1], 16;" :: "r"(saddr), "l"(gaddr));
}
__device__ __forceinline__ void cp_commit() { asm volatile("cp.async.commit_group;"); }
template <int N>
__device__ __forceinline__ void cp_wait() { asm volatile("cp.async.wait_group %0;" :: "n"(N)); }

__device__ __forceinline__ void ldsm4(uint32_t* r, uint32_t addr) {
    asm volatile("ldmatrix.sync.aligned.m8n8.x4.shared.b16 {%0,%1,%2,%3}, [%4];"
        : "=r"(r[0]), "=r"(r[1]), "=r"(r[2]), "=r"(r[3]) : "r"(addr));
}
__device__ __forceinline__ void mma16816(float* c, const uint32_t* a, uint32_t b0, uint32_t b1) {
    asm volatile("mma.sync.aligned.m16n8k16.row.col.f32.bf16.bf16.f32 "
        "{%0,%1,%2,%3}, {%4,%5,%6,%7}, {%8,%9}, {%0,%1,%2,%3};"
        : "+f"(c[0]), "+f"(c[1]), "+f"(c[2]), "+f"(c[3])
        : "r"(a[0]), "r"(a[1]), "r"(a[2]), "r"(a[3]), "r"(b0), "r"(b1));
}

// ---------------------------------------------------------------------
// Split fp32 -> (hi bf16, lo bf16)
// ---------------------------------------------------------------------
__global__ __launch_bounds__(256)
void split_bf16(const float* __restrict__ x, __nv_bfloat16* __restrict__ hi,
                __nv_bfloat16* __restrict__ lo, int n)
{
    int i = (blockIdx.x * 256 + threadIdx.x) * 4;
    if (i >= n) return;
    float4 v = *(const float4*)(x + i);
    __nv_bfloat16 h0 = __float2bfloat16(v.x);
    __nv_bfloat16 h1 = __float2bfloat16(v.y);
    __nv_bfloat16 h2 = __float2bfloat16(v.z);
    __nv_bfloat16 h3 = __float2bfloat16(v.w);
    __nv_bfloat16 l0 = __float2bfloat16(v.x - __bfloat162float(h0));
    __nv_bfloat16 l1 = __float2bfloat16(v.y - __bfloat162float(h1));
    __nv_bfloat16 l2 = __float2bfloat16(v.z - __bfloat162float(h2));
    __nv_bfloat16 l3 = __float2bfloat16(v.w - __bfloat162float(h3));
    *(__nv_bfloat162*)(hi + i)     = __nv_bfloat162(h0, h1);
    *(__nv_bfloat162*)(hi + i + 2) = __nv_bfloat162(h2, h3);
    *(__nv_bfloat162*)(lo + i)     = __nv_bfloat162(l0, l1);
    *(__nv_bfloat162*)(lo + i + 2) = __nv_bfloat162(l2, l3);
}

// ---------------------------------------------------------------------
// Tensor-core GEMM: C[M,N] = (Ah+Al)[M,K] @ (Bh+Bl)[N,K]^T + bias[N]
//   128x128 CTA tile, BK=32, 3-stage cp.async pipeline, 8 warps (64x32 each)
//   bf16 split: 3 mma products per tile (hh, hl, lh)
// SMEM per stage: A 2x10240B + B 2x10240B = 40960B; rows padded to 80B so
// ldmatrix phases (8 rows x 80B) hit 8 distinct 16B banks.
// ---------------------------------------------------------------------
#define STAGES 3
#define SSTAGE 40960
#define GEMM_SMEM (STAGES * SSTAGE)   // 122880

__global__ __launch_bounds__(256, 1)
void gemm_mma(const __nv_bfloat16* __restrict__ Ah, const __nv_bfloat16* __restrict__ Al,
              const __nv_bfloat16* __restrict__ Bh, const __nv_bfloat16* __restrict__ Bl,
              const float* __restrict__ bias, float* __restrict__ C, int N, int K)
{
    extern __shared__ __align__(128) char smem[];
    const uint32_t sbase = smem_u32(smem);

    const int tid  = threadIdx.x;
    const int lane = tid & 31;
    const int wid  = tid >> 5;
    const int bm = blockIdx.y * 128;
    const int bn = blockIdx.x * 128;

    // warp tile: 2 (m) x 4 (n) warps, each 64x32
    const int wm = (wid >> 2) * 64;
    const int wn = (wid & 3) * 32;

    // load mapping: per split 512 x 16B chunks (128 rows x 4), 2 chunks/thread
    const int lrow = (tid >> 2) & 127;        // with it*256 offset below
    // ldmatrix lane offsets (bytes within a split's tile)
    const uint32_t aoff = (uint32_t)((wm + (lane & 15)) * 80 + (lane >> 4) * 16);
    const uint32_t boff = (uint32_t)(20480 + (wn + (lane & 15)) * 80 + (lane >> 4) * 16);

    const __nv_bfloat16* Abase[2] = { Ah + (size_t)bm * K, Al + (size_t)bm * K };
    const __nv_bfloat16* Bbase[2] = { Bh + (size_t)bn * K, Bl + (size_t)bn * K };

    float c[4][4][4];
    #pragma unroll
    for (int i = 0; i < 4; i++)
        #pragma unroll
        for (int j = 0; j < 4; j++)
            #pragma unroll
            for (int q = 0; q < 4; q++) c[i][j][q] = 0.0f;

    const int nk = K >> 5;   // BK=32

    // ---- load issue for K-tile kt into slot ----
    auto issue = [&](int kt, int slot) {
        const int koff = kt * 32;
        const uint32_t st = sbase + slot * SSTAGE;
        #pragma unroll
        for (int sp = 0; sp < 2; sp++) {
            #pragma unroll
            for (int it = 0; it < 2; it++) {
                int idx = tid + it * 256;
                int row = idx >> 2;
                int c16 = idx & 3;
                cp_async16(st + sp * 10240 + row * 80 + c16 * 16,
                           Abase[sp] + (size_t)row * K + koff + c16 * 8);
                cp_async16(st + 20480 + sp * 10240 + row * 80 + c16 * 16,
                           Bbase[sp] + (size_t)row * K + koff + c16 * 8);
            }
        }
    };

    #pragma unroll
    for (int s = 0; s < STAGES - 1; s++) { issue(s, s); cp_commit(); }

    for (int kt = 0; kt < nk; kt++) {
        cp_wait<STAGES - 2>();
        __syncthreads();

        const int nxt = kt + STAGES - 1;
        if (nxt < nk) issue(nxt, nxt % STAGES);
        cp_commit();

        const uint32_t st = sbase + (kt % STAGES) * SSTAGE;
        #pragma unroll
        for (int kk = 0; kk < 2; kk++) {
            uint32_t ah[4][4], al[4][4], bh[2][4], bl[2][4];
            #pragma unroll
            for (int i = 0; i < 4; i++) {
                ldsm4(ah[i], st + aoff + i * 1280 + kk * 32);
                ldsm4(al[i], st + 10240 + aoff + i * 1280 + kk * 32);
            }
            #pragma unroll
            for (int j2 = 0; j2 < 2; j2++) {
                ldsm4(bh[j2], st + boff + j2 * 1280 + kk * 32);
                ldsm4(bl[j2], st + 10240 + boff + j2 * 1280 + kk * 32);
            }
            #pragma unroll
            for (int i = 0; i < 4; i++)
                #pragma unroll
                for (int j = 0; j < 4; j++) {
                    const int j2 = j >> 1, sl = j & 1;
                    mma16816(c[i][j], ah[i], bh[j2][sl], bh[j2][sl + 2]);
                    mma16816(c[i][j], ah[i], bl[j2][sl], bl[j2][sl + 2]);
                    mma16816(c[i][j], al[i], bh[j2][sl], bh[j2][sl + 2]);
                }
        }
        __syncthreads();
    }

    // epilogue: frag (16x8): c0,c1 at row g cols 2t,2t+1 ; c2,c3 at row g+8
    const int g = lane >> 2, t = lane & 3;
    #pragma unroll
    for (int j = 0; j < 4; j++) {
        const int col = bn + wn + j * 8 + t * 2;
        const float b0 = bias[col], b1 = bias[col + 1];
        #pragma unroll
        for (int i = 0; i < 4; i++) {
            const int row0 = bm + wm + i * 16 + g;
            float2 v0 = make_float2(c[i][j][0] + b0, c[i][j][1] + b1);
            float2 v1 = make_float2(c[i][j][2] + b0, c[i][j][3] + b1);
            *(float2*)(C + (size_t)row0 * N + col)       = v0;
            *(float2*)(C + (size_t)(row0 + 8) * N + col) = v1;
        }
    }
}

// =====================================================================
// Flash attention (causal, fp32, online softmax) — round-1 baseline
// =====================================================================
#define BR 64
#define BC 64
#define FSTR 132
#define PSTR 65
#define FLASH_SMEM (3 * BR * FSTR * (int)sizeof(float))

__device__ __forceinline__ float redmax16(float v) {
    v = fmaxf(v, __shfl_xor_sync(0xffffffffu, v, 1));
    v = fmaxf(v, __shfl_xor_sync(0xffffffffu, v, 2));
    v = fmaxf(v, __shfl_xor_sync(0xffffffffu, v, 4));
    v = fmaxf(v, __shfl_xor_sync(0xffffffffu, v, 8));
    return v;
}
__device__ __forceinline__ float redsum16(float v) {
    v += __shfl_xor_sync(0xffffffffu, v, 1);
    v += __shfl_xor_sync(0xffffffffu, v, 2);
    v += __shfl_xor_sync(0xffffffffu, v, 4);
    v += __shfl_xor_sync(0xffffffffu, v, 8);
    return v;
}

__global__ __launch_bounds__(256, 2)
void flash_attn(const float* __restrict__ qkv, float* __restrict__ ctx)
{
    extern __shared__ __align__(16) float sm[];
    float* Qs = sm;
    float* Ks = sm + BR * FSTR;
    float* Vs = sm + 2 * BR * FSTR;
    float* Ps = Ks;

    const int tid = threadIdx.x;
    const int tx = tid & 15;
    const int ty = tid >> 4;
    const int h  = blockIdx.y;
    const int qb = blockIdx.x;

    const float scale = 0.08838834764831845f;

    const float* qbase = qkv + (size_t)(qb * BR) * QKVC + h * HD;
    #pragma unroll
    for (int l = 0; l < 8; l++) {
        int idx = tid + l * 256;
        int r = idx >> 5;
        int c = (idx & 31) << 2;
        *(float4*)(Qs + r * FSTR + c) = *(const float4*)(qbase + (size_t)r * QKVC + c);
    }

    float m_i[4], l_i[4], o[4][8];
    #pragma unroll
    for (int i = 0; i < 4; i++) {
        m_i[i] = -1e30f; l_i[i] = 0.0f;
        #pragma unroll
        for (int j = 0; j < 8; j++) o[i][j] = 0.0f;
    }

    for (int kb = 0; kb <= qb; kb++) {
        __syncthreads();
        const float* kp = qkv + (size_t)(kb * BC) * QKVC + EM + h * HD;
        const float* vp = kp + EM;
        #pragma unroll
        for (int l = 0; l < 8; l++) {
            int idx = tid + l * 256;
            int r = idx >> 5;
            int c = (idx & 31) << 2;
            *(float4*)(Ks + r * FSTR + c) = *(const float4*)(kp + (size_t)r * QKVC + c);
            *(float4*)(Vs + r * FSTR + c) = *(const float4*)(vp + (size_t)r * QKVC + c);
        }
        __syncthreads();

        float s[4][4];
        #pragma unroll
        for (int i = 0; i < 4; i++)
            #pragma unroll
            for (int j = 0; j < 4; j++) s[i][j] = 0.0f;

        #pragma unroll
        for (int d = 0; d < HD; d += 4) {
            float4 aq[4], bk[4];
            #pragma unroll
            for (int i = 0; i < 4; i++) aq[i] = *(const float4*)(Qs + (ty + 16*i) * FSTR + d);
            #pragma unroll
            for (int j = 0; j < 4; j++) bk[j] = *(const float4*)(Ks + (tx + 16*j) * FSTR + d);
            #pragma unroll
            for (int i = 0; i < 4; i++)
                #pragma unroll
                for (int j = 0; j < 4; j++) {
                    s[i][j] = fmaf(aq[i].x, bk[j].x, s[i][j]);
                    s[i][j] = fmaf(aq[i].y, bk[j].y, s[i][j]);
                    s[i][j] = fmaf(aq[i].z, bk[j].z, s[i][j]);
                    s[i][j] = fmaf(aq[i].w, bk[j].w, s[i][j]);
                }
        }

        const bool diag = (kb == qb);
        #pragma unroll
        for (int i = 0; i < 4; i++) {
            const int row = ty + 16*i;
            float mloc = -1e30f;
            #pragma unroll
            for (int j = 0; j < 4; j++) {
                float v = s[i][j] * scale;
                if (diag && (tx + 16*j) > row) v = -1e30f;
                s[i][j] = v;
                mloc = fmaxf(mloc, v);
            }
            mloc = redmax16(mloc);
            const float mnew = fmaxf(m_i[i], mloc);
            float rsum = 0.0f;
            #pragma unroll
            for (int j = 0; j < 4; j++) {
                float p = __expf(s[i][j] - mnew);
                s[i][j] = p;
                rsum += p;
            }
            rsum = redsum16(rsum);
            const float f = __expf(m_i[i] - mnew);
            l_i[i] = l_i[i] * f + rsum;
            m_i[i] = mnew;
            #pragma unroll
            for (int j = 0; j < 8; j++) o[i][j] *= f;
        }

        __syncthreads();
        #pragma unroll
        for (int j = 0; j < 4; j++)
            #pragma unroll
            for (int i = 0; i < 4; i++)
                Ps[(tx + 16*j) * PSTR + (ty + 16*i)] = s[i][j];
        __syncthreads();

        #pragma unroll 4
        for (int n = 0; n < BC; n++) {
            float a[4];
            #pragma unroll
            for (int i = 0; i < 4; i++) a[i] = Ps[n * PSTR + ty + 16*i];
            float4 b0 = *(const float4*)(Vs + n * FSTR + tx*8);
            float4 b1 = *(const float4*)(Vs + n * FSTR + tx*8 + 4);
            float b[8] = {b0.x,b0.y,b0.z,b0.w,b1.x,b1.y,b1.z,b1.w};
            #pragma unroll
            for (int i = 0; i < 4; i++)
                #pragma unroll
                for (int j = 0; j < 8; j++)
                    o[i][j] = fmaf(a[i], b[j], o[i][j]);
        }
    }

    #pragma unroll
    for (int i = 0; i < 4; i++) {
        const int row = qb * BR + ty + 16*i;
        const float inv = 1.0f / l_i[i];
        float* op = ctx + (size_t)row * EM + h * HD + tx*8;
        float4 v0 = make_float4(o[i][0]*inv, o[i][1]*inv, o[i][2]*inv, o[i][3]*inv);
        float4 v1 = make_float4(o[i][4]*inv, o[i][5]*inv, o[i][6]*inv, o[i][7]*inv);
        *(float4*)(op)     = v0;
        *(float4*)(op + 4) = v1;
    }
}

// =====================================================================
extern "C" void kernel_launch(void* const* d_in, const int* in_sizes, int n_in,
                              void* d_out, int out_size)
{
    (void)in_sizes; (void)n_in; (void)out_size;
    const float* hs   = (const float*)d_in[0];
    const float* wqkv = (const float*)d_in[1];
    const float* bqkv = (const float*)d_in[2];
    const float* wo   = (const float*)d_in[3];
    const float* bo   = (const float*)d_in[4];
    float* out = (float*)d_out;

    float *qkv, *ctx;
    __nv_bfloat16 *ah, *al, *bh, *bl;
    cudaGetSymbolAddress((void**)&qkv, g_qkv);
    cudaGetSymbolAddress((void**)&ctx, g_ctx);
    cudaGetSymbolAddress((void**)&ah, g_ah);
    cudaGetSymbolAddress((void**)&al, g_al);
    cudaGetSymbolAddress((void**)&bh, g_bh);
    cudaGetSymbolAddress((void**)&bl, g_bl);

    cudaFuncSetAttribute(gemm_mma, cudaFuncAttributeMaxDynamicSharedMemorySize, GEMM_SMEM);
    cudaFuncSetAttribute(flash_attn, cudaFuncAttributeMaxDynamicSharedMemorySize, FLASH_SMEM);

    // 1) splits for QKV projection
    split_bf16<<<(SQ * EM / 4 + 255) / 256, 256>>>(hs, ah, al, SQ * EM);
    split_bf16<<<(QKVC * EM / 4 + 255) / 256, 256>>>(wqkv, bh, bl, QKVC * EM);

    // 2) QKV projection (tensor cores): qkv[S,3E] = hs @ Wqkv^T + bqkv
    dim3 g1(QKVC / 128, SQ / 128);
    gemm_mma<<<g1, 256, GEMM_SMEM>>>(ah, al, bh, bl, bqkv, qkv, QKVC, EM);

    // 3) causal flash attention -> ctx[S,E]
    dim3 g2(SQ / BR, NH);
    flash_attn<<<g2, 256, FLASH_SMEM>>>(qkv, ctx);

    // 4) splits for output projection
    split_bf16<<<(SQ * EM / 4 + 255) / 256, 256>>>(ctx, ah, al, SQ * EM);
    split_bf16<<<(EM * EM / 4 + 255) / 256, 256>>>(wo, bh, bl, EM * EM);

    // 5) output projection (tensor cores): out[S,E] = ctx @ Wo^T + bo
    dim3 g3(EM / 128, SQ / 128);
    gemm_mma<<<g3, 256, GEMM_SMEM>>>(ah, al, bh, bl, bo, out, EM, EM);
}

// round 4
// speedup vs baseline: 2.4306x; 1.8086x over previous
#include <cuda_runtime.h>
#include <cuda_bf16.h>
#include <math.h>
#include <cstdint>

#define SQ   4096
#define EM   2048
#define NH   16
#define HD   128
#define QKVC (3*EM)

// ---------------------------------------------------------------------
// Scratch (allocation-free rule: device globals)
// ---------------------------------------------------------------------
__device__ __nv_bfloat16 g_qkvh[(size_t)SQ * QKVC];   // qkv hi split
__device__ __nv_bfloat16 g_qkvl[(size_t)SQ * QKVC];   // qkv lo split
__device__ __nv_bfloat16 g_ah[(size_t)SQ * EM];       // A hi (hs, then ctx)
__device__ __nv_bfloat16 g_al[(size_t)SQ * EM];       // A lo
__device__ __nv_bfloat16 g_bh[(size_t)QKVC * EM];     // W hi (Wqkv, then Wo)
__device__ __nv_bfloat16 g_bl[(size_t)QKVC * EM];     // W lo

// ---------------------------------------------------------------------
// Portable PTX helpers (sm_80-class: valid under compute_103 target)
// ---------------------------------------------------------------------
__device__ __forceinline__ uint32_t smem_u32(const void* p) {
    uint32_t a;
    asm("{ .reg .u64 t; cvta.to.shared.u64 t, %1; cvt.u32.u64 %0, t; }" : "=r"(a) : "l"(p));
    return a;
}
__device__ __forceinline__ void cp_async16(uint32_t saddr, const void* gaddr) {
    asm volatile("cp.async.cg.shared.global [%0], [%1], 16;" :: "r"(saddr), "l"(gaddr));
}
__device__ __forceinline__ void cp_commit() { asm volatile("cp.async.commit_group;"); }
template <int N>
__device__ __forceinline__ void cp_wait() { asm volatile("cp.async.wait_group %0;" :: "n"(N)); }

__device__ __forceinline__ void ldsm4(uint32_t* r, uint32_t addr) {
    asm volatile("ldmatrix.sync.aligned.m8n8.x4.shared.b16 {%0,%1,%2,%3}, [%4];"
        : "=r"(r[0]), "=r"(r[1]), "=r"(r[2]), "=r"(r[3]) : "r"(addr));
}
__device__ __forceinline__ void ldsm4t(uint32_t* r, uint32_t addr) {
    asm volatile("ldmatrix.sync.aligned.m8n8.x4.trans.shared.b16 {%0,%1,%2,%3}, [%4];"
        : "=r"(r[0]), "=r"(r[1]), "=r"(r[2]), "=r"(r[3]) : "r"(addr));
}
__device__ __forceinline__ void mma16816(float* c, const uint32_t* a, uint32_t b0, uint32_t b1) {
    asm volatile("mma.sync.aligned.m16n8k16.row.col.f32.bf16.bf16.f32 "
        "{%0,%1,%2,%3}, {%4,%5,%6,%7}, {%8,%9}, {%0,%1,%2,%3};"
        : "+f"(c[0]), "+f"(c[1]), "+f"(c[2]), "+f"(c[3])
        : "r"(a[0]), "r"(a[1]), "r"(a[2]), "r"(a[3]), "r"(b0), "r"(b1));
}
__device__ __forceinline__ uint32_t pack_bf16(float lo, float hi) {
    __nv_bfloat162 v(__float2bfloat16(lo), __float2bfloat16(hi));
    return *reinterpret_cast<uint32_t*>(&v);
}

// ---------------------------------------------------------------------
// Split fp32 -> (hi bf16, lo bf16)
// ---------------------------------------------------------------------
__global__ __launch_bounds__(256)
void split_bf16(const float* __restrict__ x, __nv_bfloat16* __restrict__ hi,
                __nv_bfloat16* __restrict__ lo, int n)
{
    int i = (blockIdx.x * 256 + threadIdx.x) * 4;
    if (i >= n) return;
    float4 v = *(const float4*)(x + i);
    __nv_bfloat16 h0 = __float2bfloat16(v.x);
    __nv_bfloat16 h1 = __float2bfloat16(v.y);
    __nv_bfloat16 h2 = __float2bfloat16(v.z);
    __nv_bfloat16 h3 = __float2bfloat16(v.w);
    __nv_bfloat16 l0 = __float2bfloat16(v.x - __bfloat162float(h0));
    __nv_bfloat16 l1 = __float2bfloat16(v.y - __bfloat162float(h1));
    __nv_bfloat16 l2 = __float2bfloat16(v.z - __bfloat162float(h2));
    __nv_bfloat16 l3 = __float2bfloat16(v.w - __bfloat162float(h3));
    *(__nv_bfloat162*)(hi + i)     = __nv_bfloat162(h0, h1);
    *(__nv_bfloat162*)(hi + i + 2) = __nv_bfloat162(h2, h3);
    *(__nv_bfloat162*)(lo + i)     = __nv_bfloat162(l0, l1);
    *(__nv_bfloat162*)(lo + i + 2) = __nv_bfloat162(l2, l3);
}

// ---------------------------------------------------------------------
// Tensor-core GEMM: C = (Ah+Al)[M,K] @ (Bh+Bl)[N,K]^T + bias[N]
// mode 0: C fp32; mode 1: (Ch, Cl) bf16 split output
// ---------------------------------------------------------------------
#define STAGES 3
#define SSTAGE 40960
#define GEMM_SMEM (STAGES * SSTAGE)

__global__ __launch_bounds__(256, 1)
void gemm_mma(const __nv_bfloat16* __restrict__ Ah, const __nv_bfloat16* __restrict__ Al,
              const __nv_bfloat16* __restrict__ Bh, const __nv_bfloat16* __restrict__ Bl,
              const float* __restrict__ bias, float* __restrict__ C,
              __nv_bfloat16* __restrict__ Ch, __nv_bfloat16* __restrict__ Cl,
              int mode, int N, int K)
{
    extern __shared__ __align__(128) char smem[];
    const uint32_t sbase = smem_u32(smem);

    const int tid  = threadIdx.x;
    const int lane = tid & 31;
    const int wid  = tid >> 5;
    const int bm = blockIdx.y * 128;
    const int bn = blockIdx.x * 128;

    const int wm = (wid >> 2) * 64;
    const int wn = (wid & 3) * 32;

    const uint32_t aoff = (uint32_t)((wm + (lane & 15)) * 80 + (lane >> 4) * 16);
    const uint32_t boff = (uint32_t)(20480 + (wn + (lane & 15)) * 80 + (lane >> 4) * 16);

    const __nv_bfloat16* Abase[2] = { Ah + (size_t)bm * K, Al + (size_t)bm * K };
    const __nv_bfloat16* Bbase[2] = { Bh + (size_t)bn * K, Bl + (size_t)bn * K };

    float c[4][4][4];
    #pragma unroll
    for (int i = 0; i < 4; i++)
        #pragma unroll
        for (int j = 0; j < 4; j++)
            #pragma unroll
            for (int q = 0; q < 4; q++) c[i][j][q] = 0.0f;

    const int nk = K >> 5;

    auto issue = [&](int kt, int slot) {
        const int koff = kt * 32;
        const uint32_t st = sbase + slot * SSTAGE;
        #pragma unroll
        for (int sp = 0; sp < 2; sp++) {
            #pragma unroll
            for (int it = 0; it < 2; it++) {
                int idx = tid + it * 256;
                int row = idx >> 2;
                int c16 = idx & 3;
                cp_async16(st + sp * 10240 + row * 80 + c16 * 16,
                           Abase[sp] + (size_t)row * K + koff + c16 * 8);
                cp_async16(st + 20480 + sp * 10240 + row * 80 + c16 * 16,
                           Bbase[sp] + (size_t)row * K + koff + c16 * 8);
            }
        }
    };

    #pragma unroll
    for (int s = 0; s < STAGES - 1; s++) { issue(s, s); cp_commit(); }

    for (int kt = 0; kt < nk; kt++) {
        cp_wait<STAGES - 2>();
        __syncthreads();

        const int nxt = kt + STAGES - 1;
        if (nxt < nk) issue(nxt, nxt % STAGES);
        cp_commit();

        const uint32_t st = sbase + (kt % STAGES) * SSTAGE;
        #pragma unroll
        for (int kk = 0; kk < 2; kk++) {
            uint32_t ah[4][4], al[4][4], bh[2][4], bl[2][4];
            #pragma unroll
            for (int i = 0; i < 4; i++) {
                ldsm4(ah[i], st + aoff + i * 1280 + kk * 32);
                ldsm4(al[i], st + 10240 + aoff + i * 1280 + kk * 32);
            }
            #pragma unroll
            for (int j2 = 0; j2 < 2; j2++) {
                ldsm4(bh[j2], st + boff + j2 * 1280 + kk * 32);
                ldsm4(bl[j2], st + 10240 + boff + j2 * 1280 + kk * 32);
            }
            #pragma unroll
            for (int i = 0; i < 4; i++)
                #pragma unroll
                for (int j = 0; j < 4; j++) {
                    const int j2 = j >> 1, sl = j & 1;
                    mma16816(c[i][j], ah[i], bh[j2][sl], bh[j2][sl + 2]);
                    mma16816(c[i][j], ah[i], bl[j2][sl], bl[j2][sl + 2]);
                    mma16816(c[i][j], al[i], bh[j2][sl], bh[j2][sl + 2]);
                }
        }
        __syncthreads();
    }

    const int g = lane >> 2, t = lane & 3;
    #pragma unroll
    for (int j = 0; j < 4; j++) {
        const int col = bn + wn + j * 8 + t * 2;
        const float b0 = bias[col], b1 = bias[col + 1];
        #pragma unroll
        for (int i = 0; i < 4; i++) {
            const int row0 = bm + wm + i * 16 + g;
            float x0 = c[i][j][0] + b0, x1 = c[i][j][1] + b1;
            float x2 = c[i][j][2] + b0, x3 = c[i][j][3] + b1;
            if (mode == 0) {
                *(float2*)(C + (size_t)row0 * N + col)       = make_float2(x0, x1);
                *(float2*)(C + (size_t)(row0 + 8) * N + col) = make_float2(x2, x3);
            } else {
                __nv_bfloat16 h0 = __float2bfloat16(x0), h1 = __float2bfloat16(x1);
                __nv_bfloat16 h2 = __float2bfloat16(x2), h3 = __float2bfloat16(x3);
                *(__nv_bfloat162*)(Ch + (size_t)row0 * N + col) = __nv_bfloat162(h0, h1);
                *(__nv_bfloat162*)(Ch + (size_t)(row0 + 8) * N + col) = __nv_bfloat162(h2, h3);
                *(__nv_bfloat162*)(Cl + (size_t)row0 * N + col) =
                    __nv_bfloat162(__float2bfloat16(x0 - __bfloat162float(h0)),
                                   __float2bfloat16(x1 - __bfloat162float(h1)));
                *(__nv_bfloat162*)(Cl + (size_t)(row0 + 8) * N + col) =
                    __nv_bfloat162(__float2bfloat16(x2 - __bfloat162float(h2)),
                                   __float2bfloat16(x3 - __bfloat162float(h3)));
            }
        }
    }
}

// =====================================================================
// Tensorized flash attention (causal): Br=128, Bc=64, 8 warps
// QK^T and PV on mma.sync bf16 with 3-product error-compensated splits.
// Writes ctx as (hi, lo) bf16 split for the O projection.
// =====================================================================
#define ASTR 272                       // padded smem row stride (bytes)
#define QTILE (128 * ASTR)             // 34816
#define KVTILE (64 * ASTR)             // 17408
#define KVSTAGE (4 * KVTILE)           // 69632 (Kh,Kl,Vh,Vl)
#define FLASH_SMEM (2 * QTILE + 2 * KVSTAGE)   // 208896

__global__ __launch_bounds__(256, 1)
void flash_attn_mma(const __nv_bfloat16* __restrict__ qkvh,
                    const __nv_bfloat16* __restrict__ qkvl,
                    __nv_bfloat16* __restrict__ ctxh,
                    __nv_bfloat16* __restrict__ ctxl)
{
    extern __shared__ __align__(128) char smem[];
    const uint32_t sb = smem_u32(smem);

    const int tid  = threadIdx.x;
    const int lane = tid & 31;
    const int wid  = tid >> 5;
    const int h  = blockIdx.y;
    const int qb = gridDim.x - 1 - blockIdx.x;   // heavy CTAs first
    const int q0w = qb * 128 + wid * 16;         // warp's first Q row
    const int nkb = 2 * qb + 2;
    const float scale = 0.08838834764831845f;    // 1/sqrt(128)

    // ---- Q load (hi, lo) ----
    {
        const size_t qrow = (size_t)(qb * 128) * QKVC + h * HD;
        const __nv_bfloat16* qsrc[2] = { qkvh + qrow, qkvl + qrow };
        #pragma unroll
        for (int it = 0; it < 16; it++) {
            int idx = tid + it * 256;
            int sp = idx >> 11, rem = idx & 2047;
            int row = rem >> 4, ch = rem & 15;
            cp_async16(sb + sp * QTILE + row * ASTR + ch * 16,
                       qsrc[sp] + (size_t)row * QKVC + ch * 8);
        }
    }

    auto issueKV = [&](int kb, int slot) {
        const size_t roff = (size_t)(kb * 64) * QKVC + h * HD;
        const __nv_bfloat16* base[4] = { qkvh + EM + roff, qkvl + EM + roff,
                                         qkvh + 2 * EM + roff, qkvl + 2 * EM + roff };
        const uint32_t st = sb + 2 * QTILE + slot * KVSTAGE;
        #pragma unroll
        for (int it = 0; it < 16; it++) {
            int idx = tid + it * 256;
            int arr = idx >> 10, rem = idx & 1023;
            int row = rem >> 4, ch = rem & 15;
            cp_async16(st + arr * KVTILE + row * ASTR + ch * 16,
                       base[arr] + (size_t)row * QKVC + ch * 8);
        }
    };

    issueKV(0, 0); cp_commit();          // group: Q + KV0
    issueKV(1, 1); cp_commit();          // nkb >= 2 always

    float m[2] = { -1e30f, -1e30f };
    float l[2] = { 0.0f, 0.0f };
    float o[16][4];
    #pragma unroll
    for (int n = 0; n < 16; n++)
        #pragma unroll
        for (int q = 0; q < 4; q++) o[n][q] = 0.0f;

    const int g = lane >> 2, t = lane & 3;
    const uint32_t qaddr = sb + (wid * 16 + (lane & 15)) * ASTR + (lane >> 4) * 16;
    const uint32_t kvlane = (uint32_t)((lane & 15) * ASTR + (lane >> 4) * 16);

    for (int kb = 0; kb < nkb; kb++) {
        cp_wait<1>();
        __syncthreads();

        const int slot = kb & 1;
        const uint32_t kB = sb + 2 * QTILE + slot * KVSTAGE;
        const uint32_t vB = kB + 2 * KVTILE;
        const bool skip = (kb * 64 > q0w + 15);

        if (!skip) {
            // ---- S = Q K^T (3-product split) ----
            float s[8][4];
            #pragma unroll
            for (int j = 0; j < 8; j++)
                #pragma unroll
                for (int q = 0; q < 4; q++) s[j][q] = 0.0f;

            #pragma unroll
            for (int ks = 0; ks < 8; ks++) {
                uint32_t ah4[4], al4[4];
                ldsm4(ah4, qaddr + ks * 32);
                ldsm4(al4, qaddr + QTILE + ks * 32);
                #pragma unroll
                for (int p2 = 0; p2 < 4; p2++) {
                    uint32_t bh4[4], bl4[4];
                    ldsm4(bh4, kB + kvlane + p2 * (16 * ASTR) + ks * 32);
                    ldsm4(bl4, kB + KVTILE + kvlane + p2 * (16 * ASTR) + ks * 32);
                    #pragma unroll
                    for (int sl = 0; sl < 2; sl++) {
                        const int j = p2 * 2 + sl;
                        mma16816(s[j], ah4, bh4[sl], bh4[sl + 2]);
                        mma16816(s[j], ah4, bl4[sl], bl4[sl + 2]);
                        mma16816(s[j], al4, bh4[sl], bh4[sl + 2]);
                    }
                }
            }

            // ---- scale + causal mask + online softmax ----
            const bool dm = (kb * 64 + 63 > q0w);
            const int r0 = q0w + g, r1 = q0w + 8 + g;
            float mx0 = -1e30f, mx1 = -1e30f;
            #pragma unroll
            for (int j = 0; j < 8; j++) {
                const int col = kb * 64 + 8 * j + 2 * t;
                float v0 = s[j][0] * scale, v1 = s[j][1] * scale;
                float v2 = s[j][2] * scale, v3 = s[j][3] * scale;
                if (dm) {
                    if (col     > r0) v0 = -1e30f;
                    if (col + 1 > r0) v1 = -1e30f;
                    if (col     > r1) v2 = -1e30f;
                    if (col + 1 > r1) v3 = -1e30f;
                }
                s[j][0] = v0; s[j][1] = v1; s[j][2] = v2; s[j][3] = v3;
                mx0 = fmaxf(mx0, fmaxf(v0, v1));
                mx1 = fmaxf(mx1, fmaxf(v2, v3));
            }
            mx0 = fmaxf(mx0, __shfl_xor_sync(0xffffffffu, mx0, 1));
            mx0 = fmaxf(mx0, __shfl_xor_sync(0xffffffffu, mx0, 2));
            mx1 = fmaxf(mx1, __shfl_xor_sync(0xffffffffu, mx1, 1));
            mx1 = fmaxf(mx1, __shfl_xor_sync(0xffffffffu, mx1, 2));

            const float mn0 = fmaxf(m[0], mx0);
            const float mn1 = fmaxf(m[1], mx1);
            float rs0 = 0.0f, rs1 = 0.0f;
            #pragma unroll
            for (int j = 0; j < 8; j++) {
                s[j][0] = __expf(s[j][0] - mn0);
                s[j][1] = __expf(s[j][1] - mn0);
                s[j][2] = __expf(s[j][2] - mn1);
                s[j][3] = __expf(s[j][3] - mn1);
                rs0 += s[j][0] + s[j][1];
                rs1 += s[j][2] + s[j][3];
            }
            rs0 += __shfl_xor_sync(0xffffffffu, rs0, 1);
            rs0 += __shfl_xor_sync(0xffffffffu, rs0, 2);
            rs1 += __shfl_xor_sync(0xffffffffu, rs1, 1);
            rs1 += __shfl_xor_sync(0xffffffffu, rs1, 2);

            const float f0 = __expf(m[0] - mn0);
            const float f1 = __expf(m[1] - mn1);
            l[0] = l[0] * f0 + rs0; l[1] = l[1] * f1 + rs1;
            m[0] = mn0; m[1] = mn1;
            #pragma unroll
            for (int n = 0; n < 16; n++) {
                o[n][0] *= f0; o[n][1] *= f0;
                o[n][2] *= f1; o[n][3] *= f1;
            }

            // ---- O += P V (3-product split) ----
            #pragma unroll
            for (int jp = 0; jp < 4; jp++) {
                // pack P fragments (hi/lo) from s regs
                uint32_t ph[4], pl[4];
                {
                    const float* p0 = s[2 * jp];
                    const float* p1 = s[2 * jp + 1];
                    float h;
                    ph[0] = pack_bf16(p0[0], p0[1]);
                    ph[1] = pack_bf16(p0[2], p0[3]);
                    ph[2] = pack_bf16(p1[0], p1[1]);
                    ph[3] = pack_bf16(p1[2], p1[3]);
                    __nv_bfloat162* hp;
                    hp = (__nv_bfloat162*)&ph[0];
                    pl[0] = pack_bf16(p0[0] - __bfloat162float(hp->x), p0[1] - __bfloat162float(hp->y));
                    hp = (__nv_bfloat162*)&ph[1];
                    pl[1] = pack_bf16(p0[2] - __bfloat162float(hp->x), p0[3] - __bfloat162float(hp->y));
                    hp = (__nv_bfloat162*)&ph[2];
                    pl[2] = pack_bf16(p1[0] - __bfloat162float(hp->x), p1[1] - __bfloat162float(hp->y));
                    hp = (__nv_bfloat162*)&ph[3];
                    pl[3] = pack_bf16(p1[2] - __bfloat162float(hp->x), p1[3] - __bfloat162float(hp->y));
                    (void)h;
                }
                #pragma unroll
                for (int np = 0; np < 8; np++) {
                    uint32_t bh4[4], bl4[4];
                    ldsm4t(bh4, vB + kvlane + jp * (16 * ASTR) + np * 32);
                    ldsm4t(bl4, vB + KVTILE + kvlane + jp * (16 * ASTR) + np * 32);
                    mma16816(o[2 * np],     ph, bh4[0], bh4[1]);
                    mma16816(o[2 * np],     ph, bl4[0], bl4[1]);
                    mma16816(o[2 * np],     pl, bh4[0], bh4[1]);
                    mma16816(o[2 * np + 1], ph, bh4[2], bh4[3]);
                    mma16816(o[2 * np + 1], ph, bl4[2], bl4[3]);
                    mma16816(o[2 * np + 1], pl, bh4[2], bh4[3]);
                }
            }
        }

        __syncthreads();
        if (kb + 2 < nkb) issueKV(kb + 2, slot);
        cp_commit();
    }

    // ---- epilogue: ctx = O / l, written as bf16 (hi, lo) split ----
    const float inv0 = 1.0f / l[0];
    const float inv1 = 1.0f / l[1];
    const int r0 = q0w + g, r1 = q0w + 8 + g;
    #pragma unroll
    for (int n = 0; n < 16; n++) {
        const int col = h * HD + n * 8 + 2 * t;
        float x0 = o[n][0] * inv0, x1 = o[n][1] * inv0;
        float x2 = o[n][2] * inv1, x3 = o[n][3] * inv1;
        __nv_bfloat16 h0 = __float2bfloat16(x0), h1 = __float2bfloat16(x1);
        __nv_bfloat16 h2 = __float2bfloat16(x2), h3 = __float2bfloat16(x3);
        *(__nv_bfloat162*)(ctxh + (size_t)r0 * EM + col) = __nv_bfloat162(h0, h1);
        *(__nv_bfloat162*)(ctxh + (size_t)r1 * EM + col) = __nv_bfloat162(h2, h3);
        *(__nv_bfloat162*)(ctxl + (size_t)r0 * EM + col) =
            __nv_bfloat162(__float2bfloat16(x0 - __bfloat162float(h0)),
                           __float2bfloat16(x1 - __bfloat162float(h1)));
        *(__nv_bfloat162*)(ctxl + (size_t)r1 * EM + col) =
            __nv_bfloat162(__float2bfloat16(x2 - __bfloat162float(h2)),
                           __float2bfloat16(x3 - __bfloat162float(h3)));
    }
}

// =====================================================================
extern "C" void kernel_launch(void* const* d_in, const int* in_sizes, int n_in,
                              void* d_out, int out_size)
{
    (void)in_sizes; (void)n_in; (void)out_size;
    const float* hs   = (const float*)d_in[0];
    const float* wqkv = (const float*)d_in[1];
    const float* bqkv = (const float*)d_in[2];
    const float* wo   = (const float*)d_in[3];
    const float* bo   = (const float*)d_in[4];
    float* out = (float*)d_out;

    __nv_bfloat16 *qkvh, *qkvl, *ah, *al, *bh, *bl;
    cudaGetSymbolAddress((void**)&qkvh, g_qkvh);
    cudaGetSymbolAddress((void**)&qkvl, g_qkvl);
    cudaGetSymbolAddress((void**)&ah, g_ah);
    cudaGetSymbolAddress((void**)&al, g_al);
    cudaGetSymbolAddress((void**)&bh, g_bh);
    cudaGetSymbolAddress((void**)&bl, g_bl);

    cudaFuncSetAttribute(gemm_mma, cudaFuncAttributeMaxDynamicSharedMemorySize, GEMM_SMEM);
    cudaFuncSetAttribute(flash_attn_mma, cudaFuncAttributeMaxDynamicSharedMemorySize, FLASH_SMEM);

    // 1) splits for QKV projection
    split_bf16<<<(SQ * EM / 4 + 255) / 256, 256>>>(hs, ah, al, SQ * EM);
    split_bf16<<<(QKVC * EM / 4 + 255) / 256, 256>>>(wqkv, bh, bl, QKVC * EM);

    // 2) QKV projection -> bf16 split output (fused)
    dim3 g1(QKVC / 128, SQ / 128);
    gemm_mma<<<g1, 256, GEMM_SMEM>>>(ah, al, bh, bl, bqkv, nullptr, qkvh, qkvl, 1, QKVC, EM);

    // 3) split Wo (safe: gemm1 done with bh/bl by stream order)
    split_bf16<<<(EM * EM / 4 + 255) / 256, 256>>>(wo, bh, bl, EM * EM);

    // 4) tensorized causal flash attention -> ctx as bf16 split (overwrites ah/al)
    dim3 g2(SQ / 128, NH);
    flash_attn_mma<<<g2, 256, FLASH_SMEM>>>(qkvh, qkvl, ah, al);

    // 5) output projection -> fp32 out
    dim3 g3(EM / 128, SQ / 128);
    gemm_mma<<<g3, 256, GEMM_SMEM>>>(ah, al, bh, bl, bo, out, nullptr, nullptr, 0, EM, EM);
}

// round 5
// speedup vs baseline: 2.4362x; 1.0023x over previous
#include <cuda_runtime.h>
#include <cuda_bf16.h>
#include <math.h>
#include <cstdint>

#define SQ   4096
#define EM   2048
#define NH   16
#define HD   128
#define QKVC (3*EM)

// ---------------------------------------------------------------------
// Scratch (allocation-free rule: device globals)
// ---------------------------------------------------------------------
__device__ __nv_bfloat16 g_qkvh[(size_t)SQ * QKVC];   // qkv hi split
__device__ __nv_bfloat16 g_qkvl[(size_t)SQ * QKVC];   // qkv lo split
__device__ __nv_bfloat16 g_ah[(size_t)SQ * EM];       // A hi (hs, then ctx)
__device__ __nv_bfloat16 g_al[(size_t)SQ * EM];       // A lo
__device__ __nv_bfloat16 g_bh[(size_t)QKVC * EM];     // W hi (Wqkv, then Wo)
__device__ __nv_bfloat16 g_bl[(size_t)QKVC * EM];     // W lo

// ---------------------------------------------------------------------
// Portable PTX helpers
// ---------------------------------------------------------------------
__device__ __forceinline__ uint32_t smem_u32(const void* p) {
    uint32_t a;
    asm("{ .reg .u64 t; cvta.to.shared.u64 t, %1; cvt.u32.u64 %0, t; }" : "=r"(a) : "l"(p));
    return a;
}
__device__ __forceinline__ void cp_async16(uint32_t saddr, const void* gaddr) {
    asm volatile("cp.async.cg.shared.global [%0], [%1], 16;" :: "r"(saddr), "l"(gaddr));
}
__device__ __forceinline__ void cp_commit() { asm volatile("cp.async.commit_group;"); }
template <int N>
__device__ __forceinline__ void cp_wait() { asm volatile("cp.async.wait_group %0;" :: "n"(N)); }

__device__ __forceinline__ void ldsm4(uint32_t* r, uint32_t addr) {
    asm volatile("ldmatrix.sync.aligned.m8n8.x4.shared.b16 {%0,%1,%2,%3}, [%4];"
        : "=r"(r[0]), "=r"(r[1]), "=r"(r[2]), "=r"(r[3]) : "r"(addr));
}
__device__ __forceinline__ void ldsm4t(uint32_t* r, uint32_t addr) {
    asm volatile("ldmatrix.sync.aligned.m8n8.x4.trans.shared.b16 {%0,%1,%2,%3}, [%4];"
        : "=r"(r[0]), "=r"(r[1]), "=r"(r[2]), "=r"(r[3]) : "r"(addr));
}
__device__ __forceinline__ void mma16816(float* c, const uint32_t* a, uint32_t b0, uint32_t b1) {
    asm volatile("mma.sync.aligned.m16n8k16.row.col.f32.bf16.bf16.f32 "
        "{%0,%1,%2,%3}, {%4,%5,%6,%7}, {%8,%9}, {%0,%1,%2,%3};"
        : "+f"(c[0]), "+f"(c[1]), "+f"(c[2]), "+f"(c[3])
        : "r"(a[0]), "r"(a[1]), "r"(a[2]), "r"(a[3]), "r"(b0), "r"(b1));
}
__device__ __forceinline__ uint32_t pack_bf16(float lo, float hi) {
    __nv_bfloat162 v(__float2bfloat16(lo), __float2bfloat16(hi));
    return *reinterpret_cast<uint32_t*>(&v);
}

// ---------------------------------------------------------------------
// Split fp32 -> (hi bf16, lo bf16)
// ---------------------------------------------------------------------
__global__ __launch_bounds__(256)
void split_bf16(const float* __restrict__ x, __nv_bfloat16* __restrict__ hi,
                __nv_bfloat16* __restrict__ lo, int n)
{
    int i = (blockIdx.x * 256 + threadIdx.x) * 4;
    if (i >= n) return;
    float4 v = *(const float4*)(x + i);
    __nv_bfloat16 h0 = __float2bfloat16(v.x);
    __nv_bfloat16 h1 = __float2bfloat16(v.y);
    __nv_bfloat16 h2 = __float2bfloat16(v.z);
    __nv_bfloat16 h3 = __float2bfloat16(v.w);
    __nv_bfloat16 l0 = __float2bfloat16(v.x - __bfloat162float(h0));
    __nv_bfloat16 l1 = __float2bfloat16(v.y - __bfloat162float(h1));
    __nv_bfloat16 l2 = __float2bfloat16(v.z - __bfloat162float(h2));
    __nv_bfloat16 l3 = __float2bfloat16(v.w - __bfloat162float(h3));
    *(__nv_bfloat162*)(hi + i)     = __nv_bfloat162(h0, h1);
    *(__nv_bfloat162*)(hi + i + 2) = __nv_bfloat162(h2, h3);
    *(__nv_bfloat162*)(lo + i)     = __nv_bfloat162(l0, l1);
    *(__nv_bfloat162*)(lo + i + 2) = __nv_bfloat162(l2, l3);
}

// ---------------------------------------------------------------------
// Tensor-core GEMM: C = (Ah+Al)[M,K] @ (Bh+Bl)[N,K]^T + bias[N]
// mode 0: C fp32; mode 1: (Ch, Cl) bf16 split output
// 4-stage cp.async pipeline, banded CTA swizzle (8 bm rows / band),
// single __syncthreads per K-tile.
// ---------------------------------------------------------------------
#define STAGES 4
#define SSTAGE 40960
#define GEMM_SMEM (STAGES * SSTAGE)   // 163840

__global__ __launch_bounds__(256, 1)
void gemm_mma(const __nv_bfloat16* __restrict__ Ah, const __nv_bfloat16* __restrict__ Al,
              const __nv_bfloat16* __restrict__ Bh, const __nv_bfloat16* __restrict__ Bl,
              const float* __restrict__ bias, float* __restrict__ C,
              __nv_bfloat16* __restrict__ Ch, __nv_bfloat16* __restrict__ Cl,
              int mode, int N, int K)
{
    extern __shared__ __align__(128) char smem[];
    const uint32_t sbase = smem_u32(smem);

    const int tid  = threadIdx.x;
    const int lane = tid & 31;
    const int wid  = tid >> 5;

    // ---- banded CTA swizzle: waves cover 8 bm-rows x ~19 bn-cols ----
    const int id    = blockIdx.y * gridDim.x + blockIdx.x;
    const int bandw = 8 * gridDim.x;
    const int band  = id / bandw;
    const int rem   = id - band * bandw;
    const int bm = (band * 8 + (rem & 7)) * 128;
    const int bn = (rem >> 3) * 128;

    const int wm = (wid >> 2) * 64;
    const int wn = (wid & 3) * 32;

    const uint32_t aoff = (uint32_t)((wm + (lane & 15)) * 80 + (lane >> 4) * 16);
    const uint32_t boff = (uint32_t)(20480 + (wn + (lane & 15)) * 80 + (lane >> 4) * 16);

    const __nv_bfloat16* Abase[2] = { Ah + (size_t)bm * K, Al + (size_t)bm * K };
    const __nv_bfloat16* Bbase[2] = { Bh + (size_t)bn * K, Bl + (size_t)bn * K };

    float c[4][4][4];
    #pragma unroll
    for (int i = 0; i < 4; i++)
        #pragma unroll
        for (int j = 0; j < 4; j++)
            #pragma unroll
            for (int q = 0; q < 4; q++) c[i][j][q] = 0.0f;

    const int nk = K >> 5;

    auto issue = [&](int kt, int slot) {
        const int koff = kt * 32;
        const uint32_t st = sbase + slot * SSTAGE;
        #pragma unroll
        for (int sp = 0; sp < 2; sp++) {
            #pragma unroll
            for (int it = 0; it < 2; it++) {
                int idx = tid + it * 256;
                int row = idx >> 2;
                int c16 = idx & 3;
                cp_async16(st + sp * 10240 + row * 80 + c16 * 16,
                           Abase[sp] + (size_t)row * K + koff + c16 * 8);
                cp_async16(st + 20480 + sp * 10240 + row * 80 + c16 * 16,
                           Bbase[sp] + (size_t)row * K + koff + c16 * 8);
            }
        }
    };

    #pragma unroll
    for (int s = 0; s < STAGES - 1; s++) { issue(s, s); cp_commit(); }

    for (int kt = 0; kt < nk; kt++) {
        cp_wait<STAGES - 2>();
        __syncthreads();   // orders prior iteration's smem reads before refill below

        const int nxt = kt + STAGES - 1;
        if (nxt < nk) issue(nxt, nxt % STAGES);
        cp_commit();

        const uint32_t st = sbase + (kt % STAGES) * SSTAGE;
        #pragma unroll
        for (int kk = 0; kk < 2; kk++) {
            uint32_t ah[4][4], al[4][4], bh[2][4], bl[2][4];
            #pragma unroll
            for (int i = 0; i < 4; i++) {
                ldsm4(ah[i], st + aoff + i * 1280 + kk * 32);
                ldsm4(al[i], st + 10240 + aoff + i * 1280 + kk * 32);
            }
            #pragma unroll
            for (int j2 = 0; j2 < 2; j2++) {
                ldsm4(bh[j2], st + boff + j2 * 1280 + kk * 32);
                ldsm4(bl[j2], st + 10240 + boff + j2 * 1280 + kk * 32);
            }
            #pragma unroll
            for (int i = 0; i < 4; i++)
                #pragma unroll
                for (int j = 0; j < 4; j++) {
                    const int j2 = j >> 1, sl = j & 1;
                    mma16816(c[i][j], ah[i], bh[j2][sl], bh[j2][sl + 2]);
                    mma16816(c[i][j], ah[i], bl[j2][sl], bl[j2][sl + 2]);
                    mma16816(c[i][j], al[i], bh[j2][sl], bh[j2][sl + 2]);
                }
        }
    }

    const int g = lane >> 2, t = lane & 3;
    #pragma unroll
    for (int j = 0; j < 4; j++) {
        const int col = bn + wn + j * 8 + t * 2;
        const float b0 = bias[col], b1 = bias[col + 1];
        #pragma unroll
        for (int i = 0; i < 4; i++) {
            const int row0 = bm + wm + i * 16 + g;
            float x0 = c[i][j][0] + b0, x1 = c[i][j][1] + b1;
            float x2 = c[i][j][2] + b0, x3 = c[i][j][3] + b1;
            if (mode == 0) {
                *(float2*)(C + (size_t)row0 * N + col)       = make_float2(x0, x1);
                *(float2*)(C + (size_t)(row0 + 8) * N + col) = make_float2(x2, x3);
            } else {
                __nv_bfloat16 h0 = __float2bfloat16(x0), h1 = __float2bfloat16(x1);
                __nv_bfloat16 h2 = __float2bfloat16(x2), h3 = __float2bfloat16(x3);
                *(__nv_bfloat162*)(Ch + (size_t)row0 * N + col) = __nv_bfloat162(h0, h1);
                *(__nv_bfloat162*)(Ch + (size_t)(row0 + 8) * N + col) = __nv_bfloat162(h2, h3);
                *(__nv_bfloat162*)(Cl + (size_t)row0 * N + col) =
                    __nv_bfloat162(__float2bfloat16(x0 - __bfloat162float(h0)),
                                   __float2bfloat16(x1 - __bfloat162float(h1)));
                *(__nv_bfloat162*)(Cl + (size_t)(row0 + 8) * N + col) =
                    __nv_bfloat162(__float2bfloat16(x2 - __bfloat162float(h2)),
                                   __float2bfloat16(x3 - __bfloat162float(h3)));
            }
        }
    }
}

// =====================================================================
// Tensorized flash attention (causal): Br=128, Bc=64, 8 warps
// =====================================================================
#define ASTR 272
#define QTILE (128 * ASTR)
#define KVTILE (64 * ASTR)
#define KVSTAGE (4 * KVTILE)
#define FLASH_SMEM (2 * QTILE + 2 * KVSTAGE)   // 208896

__global__ __launch_bounds__(256, 1)
void flash_attn_mma(const __nv_bfloat16* __restrict__ qkvh,
                    const __nv_bfloat16* __restrict__ qkvl,
                    __nv_bfloat16* __restrict__ ctxh,
                    __nv_bfloat16* __restrict__ ctxl)
{
    extern __shared__ __align__(128) char smem[];
    const uint32_t sb = smem_u32(smem);

    const int tid  = threadIdx.x;
    const int lane = tid & 31;
    const int wid  = tid >> 5;
    const int h  = blockIdx.y;
    const int qb = gridDim.x - 1 - blockIdx.x;
    const int q0w = qb * 128 + wid * 16;
    const int nkb = 2 * qb + 2;
    const float scale = 0.08838834764831845f;

    {
        const size_t qrow = (size_t)(qb * 128) * QKVC + h * HD;
        const __nv_bfloat16* qsrc[2] = { qkvh + qrow, qkvl + qrow };
        #pragma unroll
        for (int it = 0; it < 16; it++) {
            int idx = tid + it * 256;
            int sp = idx >> 11, rem = idx & 2047;
            int row = rem >> 4, ch = rem & 15;
            cp_async16(sb + sp * QTILE + row * ASTR + ch * 16,
                       qsrc[sp] + (size_t)row * QKVC + ch * 8);
        }
    }

    auto issueKV = [&](int kb, int slot) {
        const size_t roff = (size_t)(kb * 64) * QKVC + h * HD;
        const __nv_bfloat16* base[4] = { qkvh + EM + roff, qkvl + EM + roff,
                                         qkvh + 2 * EM + roff, qkvl + 2 * EM + roff };
        const uint32_t st = sb + 2 * QTILE + slot * KVSTAGE;
        #pragma unroll
        for (int it = 0; it < 16; it++) {
            int idx = tid + it * 256;
            int arr = idx >> 10, rem = idx & 1023;
            int row = rem >> 4, ch = rem & 15;
            cp_async16(st + arr * KVTILE + row * ASTR + ch * 16,
                       base[arr] + (size_t)row * QKVC + ch * 8);
        }
    };

    issueKV(0, 0); cp_commit();
    issueKV(1, 1); cp_commit();

    float m[2] = { -1e30f, -1e30f };
    float l[2] = { 0.0f, 0.0f };
    float o[16][4];
    #pragma unroll
    for (int n = 0; n < 16; n++)
        #pragma unroll
        for (int q = 0; q < 4; q++) o[n][q] = 0.0f;

    const int g = lane >> 2, t = lane & 3;
    const uint32_t qaddr = sb + (wid * 16 + (lane & 15)) * ASTR + (lane >> 4) * 16;
    const uint32_t kvlane = (uint32_t)((lane & 15) * ASTR + (lane >> 4) * 16);

    for (int kb = 0; kb < nkb; kb++) {
        cp_wait<1>();
        __syncthreads();

        const int slot = kb & 1;
        const uint32_t kB = sb + 2 * QTILE + slot * KVSTAGE;
        const uint32_t vB = kB + 2 * KVTILE;
        const bool skip = (kb * 64 > q0w + 15);

        if (!skip) {
            float s[8][4];
            #pragma unroll
            for (int j = 0; j < 8; j++)
                #pragma unroll
                for (int q = 0; q < 4; q++) s[j][q] = 0.0f;

            #pragma unroll
            for (int ks = 0; ks < 8; ks++) {
                uint32_t ah4[4], al4[4];
                ldsm4(ah4, qaddr + ks * 32);
                ldsm4(al4, qaddr + QTILE + ks * 32);
                #pragma unroll
                for (int p2 = 0; p2 < 4; p2++) {
                    uint32_t bh4[4], bl4[4];
                    ldsm4(bh4, kB + kvlane + p2 * (16 * ASTR) + ks * 32);
                    ldsm4(bl4, kB + KVTILE + kvlane + p2 * (16 * ASTR) + ks * 32);
                    #pragma unroll
                    for (int sl = 0; sl < 2; sl++) {
                        const int j = p2 * 2 + sl;
                        mma16816(s[j], ah4, bh4[sl], bh4[sl + 2]);
                        mma16816(s[j], ah4, bl4[sl], bl4[sl + 2]);
                        mma16816(s[j], al4, bh4[sl], bh4[sl + 2]);
                    }
                }
            }

            const bool dm = (kb * 64 + 63 > q0w);
            const int r0 = q0w + g, r1 = q0w + 8 + g;
            float mx0 = -1e30f, mx1 = -1e30f;
            #pragma unroll
            for (int j = 0; j < 8; j++) {
                const int col = kb * 64 + 8 * j + 2 * t;
                float v0 = s[j][0] * scale, v1 = s[j][1] * scale;
                float v2 = s[j][2] * scale, v3 = s[j][3] * scale;
                if (dm) {
                    if (col     > r0) v0 = -1e30f;
                    if (col + 1 > r0) v1 = -1e30f;
                    if (col     > r1) v2 = -1e30f;
                    if (col + 1 > r1) v3 = -1e30f;
                }
                s[j][0] = v0; s[j][1] = v1; s[j][2] = v2; s[j][3] = v3;
                mx0 = fmaxf(mx0, fmaxf(v0, v1));
                mx1 = fmaxf(mx1, fmaxf(v2, v3));
            }
            mx0 = fmaxf(mx0, __shfl_xor_sync(0xffffffffu, mx0, 1));
            mx0 = fmaxf(mx0, __shfl_xor_sync(0xffffffffu, mx0, 2));
            mx1 = fmaxf(mx1, __shfl_xor_sync(0xffffffffu, mx1, 1));
            mx1 = fmaxf(mx1, __shfl_xor_sync(0xffffffffu, mx1, 2));

            const float mn0 = fmaxf(m[0], mx0);
            const float mn1 = fmaxf(m[1], mx1);
            float rs0 = 0.0f, rs1 = 0.0f;
            #pragma unroll
            for (int j = 0; j < 8; j++) {
                s[j][0] = __expf(s[j][0] - mn0);
                s[j][1] = __expf(s[j][1] - mn0);
                s[j][2] = __expf(s[j][2] - mn1);
                s[j][3] = __expf(s[j][3] - mn1);
                rs0 += s[j][0] + s[j][1];
                rs1 += s[j][2] + s[j][3];
            }
            rs0 += __shfl_xor_sync(0xffffffffu, rs0, 1);
            rs0 += __shfl_xor_sync(0xffffffffu, rs0, 2);
            rs1 += __shfl_xor_sync(0xffffffffu, rs1, 1);
            rs1 += __shfl_xor_sync(0xffffffffu, rs1, 2);

            const float f0 = __expf(m[0] - mn0);
            const float f1 = __expf(m[1] - mn1);
            l[0] = l[0] * f0 + rs0; l[1] = l[1] * f1 + rs1;
            m[0] = mn0; m[1] = mn1;
            #pragma unroll
            for (int n = 0; n < 16; n++) {
                o[n][0] *= f0; o[n][1] *= f0;
                o[n][2] *= f1; o[n][3] *= f1;
            }

            #pragma unroll
            for (int jp = 0; jp < 4; jp++) {
                uint32_t ph[4], pl[4];
                {
                    const float* p0 = s[2 * jp];
                    const float* p1 = s[2 * jp + 1];
                    ph[0] = pack_bf16(p0[0], p0[1]);
                    ph[1] = pack_bf16(p0[2], p0[3]);
                    ph[2] = pack_bf16(p1[0], p1[1]);
                    ph[3] = pack_bf16(p1[2], p1[3]);
                    __nv_bfloat162* hp;
                    hp = (__nv_bfloat162*)&ph[0];
                    pl[0] = pack_bf16(p0[0] - __bfloat162float(hp->x), p0[1] - __bfloat162float(hp->y));
                    hp = (__nv_bfloat162*)&ph[1];
                    pl[1] = pack_bf16(p0[2] - __bfloat162float(hp->x), p0[3] - __bfloat162float(hp->y));
                    hp = (__nv_bfloat162*)&ph[2];
                    pl[2] = pack_bf16(p1[0] - __bfloat162float(hp->x), p1[1] - __bfloat162float(hp->y));
                    hp = (__nv_bfloat162*)&ph[3];
                    pl[3] = pack_bf16(p1[2] - __bfloat162float(hp->x), p1[3] - __bfloat162float(hp->y));
                }
                #pragma unroll
                for (int np = 0; np < 8; np++) {
                    uint32_t bh4[4], bl4[4];
                    ldsm4t(bh4, vB + kvlane + jp * (16 * ASTR) + np * 32);
                    ldsm4t(bl4, vB + KVTILE + kvlane + jp * (16 * ASTR) + np * 32);
                    mma16816(o[2 * np],     ph, bh4[0], bh4[1]);
                    mma16816(o[2 * np],     ph, bl4[0], bl4[1]);
                    mma16816(o[2 * np],     pl, bh4[0], bh4[1]);
                    mma16816(o[2 * np + 1], ph, bh4[2], bh4[3]);
                    mma16816(o[2 * np + 1], ph, bl4[2], bl4[3]);
                    mma16816(o[2 * np + 1], pl, bh4[2], bh4[3]);
                }
            }
        }

        __syncthreads();
        if (kb + 2 < nkb) issueKV(kb + 2, slot);
        cp_commit();
    }

    const float inv0 = 1.0f / l[0];
    const float inv1 = 1.0f / l[1];
    const int r0 = q0w + g, r1 = q0w + 8 + g;
    #pragma unroll
    for (int n = 0; n < 16; n++) {
        const int col = h * HD + n * 8 + 2 * t;
        float x0 = o[n][0] * inv0, x1 = o[n][1] * inv0;
        float x2 = o[n][2] * inv1, x3 = o[n][3] * inv1;
        __nv_bfloat16 h0 = __float2bfloat16(x0), h1 = __float2bfloat16(x1);
        __nv_bfloat16 h2 = __float2bfloat16(x2), h3 = __float2bfloat16(x3);
        *(__nv_bfloat162*)(ctxh + (size_t)r0 * EM + col) = __nv_bfloat162(h0, h1);
        *(__nv_bfloat162*)(ctxh + (size_t)r1 * EM + col) = __nv_bfloat162(h2, h3);
        *(__nv_bfloat162*)(ctxl + (size_t)r0 * EM + col) =
            __nv_bfloat162(__float2bfloat16(x0 - __bfloat162float(h0)),
                           __float2bfloat16(x1 - __bfloat162float(h1)));
        *(__nv_bfloat162*)(ctxl + (size_t)r1 * EM + col) =
            __nv_bfloat162(__float2bfloat16(x2 - __bfloat162float(h2)),
                           __float2bfloat16(x3 - __bfloat162float(h3)));
    }
}

// =====================================================================
extern "C" void kernel_launch(void* const* d_in, const int* in_sizes, int n_in,
                              void* d_out, int out_size)
{
    (void)in_sizes; (void)n_in; (void)out_size;
    const float* hs   = (const float*)d_in[0];
    const float* wqkv = (const float*)d_in[1];
    const float* bqkv = (const float*)d_in[2];
    const float* wo   = (const float*)d_in[3];
    const float* bo   = (const float*)d_in[4];
    float* out = (float*)d_out;

    __nv_bfloat16 *qkvh, *qkvl, *ah, *al, *bh, *bl;
    cudaGetSymbolAddress((void**)&qkvh, g_qkvh);
    cudaGetSymbolAddress((void**)&qkvl, g_qkvl);
    cudaGetSymbolAddress((void**)&ah, g_ah);
    cudaGetSymbolAddress((void**)&al, g_al);
    cudaGetSymbolAddress((void**)&bh, g_bh);
    cudaGetSymbolAddress((void**)&bl, g_bl);

    cudaFuncSetAttribute(gemm_mma, cudaFuncAttributeMaxDynamicSharedMemorySize, GEMM_SMEM);
    cudaFuncSetAttribute(flash_attn_mma, cudaFuncAttributeMaxDynamicSharedMemorySize, FLASH_SMEM);

    // 1) splits for QKV projection
    split_bf16<<<(SQ * EM / 4 + 255) / 256, 256>>>(hs, ah, al, SQ * EM);
    split_bf16<<<(QKVC * EM / 4 + 255) / 256, 256>>>(wqkv, bh, bl, QKVC * EM);

    // 2) QKV projection -> bf16 split output (fused)
    dim3 g1(QKVC / 128, SQ / 128);
    gemm_mma<<<g1, 256, GEMM_SMEM>>>(ah, al, bh, bl, bqkv, nullptr, qkvh, qkvl, 1, QKVC, EM);

    // 3) split Wo
    split_bf16<<<(EM * EM / 4 + 255) / 256, 256>>>(wo, bh, bl, EM * EM);

    // 4) tensorized causal flash attention -> ctx as bf16 split
    dim3 g2(SQ / 128, NH);
    flash_attn_mma<<<g2, 256, FLASH_SMEM>>>(qkvh, qkvl, ah, al);

    // 5) output projection -> fp32 out
    dim3 g3(EM / 128, SQ / 128);
    gemm_mma<<<g3, 256, GEMM_SMEM>>>(ah, al, bh, bl, bo, out, nullptr, nullptr, 0, EM, EM);
}

// round 6
// speedup vs baseline: 2.6210x; 1.0758x over previous
#include <cuda_runtime.h>
#include <cuda_bf16.h>
#include <math.h>
#include <cstdint>

#define SQ   4096
#define EM   2048
#define NH   16
#define HD   128
#define QKVC (3*EM)

// ---------------------------------------------------------------------
// Scratch (allocation-free rule: device globals)
// ---------------------------------------------------------------------
__device__ __nv_bfloat16 g_qkvh[(size_t)SQ * QKVC];   // qkv hi split
__device__ __nv_bfloat16 g_qkvl[(size_t)SQ * QKVC];   // qkv lo split
__device__ __nv_bfloat16 g_ah[(size_t)SQ * EM];       // A hi (hs, then ctx)
__device__ __nv_bfloat16 g_al[(size_t)SQ * EM];       // A lo
__device__ __nv_bfloat16 g_bh[(size_t)QKVC * EM];     // W hi (Wqkv, then Wo)
__device__ __nv_bfloat16 g_bl[(size_t)QKVC * EM];     // W lo

// ---------------------------------------------------------------------
// Portable PTX helpers
// ---------------------------------------------------------------------
__device__ __forceinline__ uint32_t smem_u32(const void* p) {
    uint32_t a;
    asm("{ .reg .u64 t; cvta.to.shared.u64 t, %1; cvt.u32.u64 %0, t; }" : "=r"(a) : "l"(p));
    return a;
}
__device__ __forceinline__ void cp_async16(uint32_t saddr, const void* gaddr) {
    asm volatile("cp.async.cg.shared.global [%0], [%1], 16;" :: "r"(saddr), "l"(gaddr));
}
__device__ __forceinline__ void cp_commit() { asm volatile("cp.async.commit_group;"); }
template <int N>
__device__ __forceinline__ void cp_wait() { asm volatile("cp.async.wait_group %0;" :: "n"(N)); }

__device__ __forceinline__ void ldsm4(uint32_t* r, uint32_t addr) {
    asm volatile("ldmatrix.sync.aligned.m8n8.x4.shared.b16 {%0,%1,%2,%3}, [%4];"
        : "=r"(r[0]), "=r"(r[1]), "=r"(r[2]), "=r"(r[3]) : "r"(addr));
}
__device__ __forceinline__ void ldsm4t(uint32_t* r, uint32_t addr) {
    asm volatile("ldmatrix.sync.aligned.m8n8.x4.trans.shared.b16 {%0,%1,%2,%3}, [%4];"
        : "=r"(r[0]), "=r"(r[1]), "=r"(r[2]), "=r"(r[3]) : "r"(addr));
}
__device__ __forceinline__ void mma16816(float* c, const uint32_t* a, uint32_t b0, uint32_t b1) {
    asm volatile("mma.sync.aligned.m16n8k16.row.col.f32.bf16.bf16.f32 "
        "{%0,%1,%2,%3}, {%4,%5,%6,%7}, {%8,%9}, {%0,%1,%2,%3};"
        : "+f"(c[0]), "+f"(c[1]), "+f"(c[2]), "+f"(c[3])
        : "r"(a[0]), "r"(a[1]), "r"(a[2]), "r"(a[3]), "r"(b0), "r"(b1));
}
__device__ __forceinline__ uint32_t pack_bf16(float lo, float hi) {
    __nv_bfloat162 v(__float2bfloat16(lo), __float2bfloat16(hi));
    return *reinterpret_cast<uint32_t*>(&v);
}

// ---------------------------------------------------------------------
// Split fp32 -> (hi bf16, lo bf16)
// ---------------------------------------------------------------------
__global__ __launch_bounds__(256)
void split_bf16(const float* __restrict__ x, __nv_bfloat16* __restrict__ hi,
                __nv_bfloat16* __restrict__ lo, int n)
{
    int i = (blockIdx.x * 256 + threadIdx.x) * 4;
    if (i >= n) return;
    float4 v = *(const float4*)(x + i);
    __nv_bfloat16 h0 = __float2bfloat16(v.x);
    __nv_bfloat16 h1 = __float2bfloat16(v.y);
    __nv_bfloat16 h2 = __float2bfloat16(v.z);
    __nv_bfloat16 h3 = __float2bfloat16(v.w);
    __nv_bfloat16 l0 = __float2bfloat16(v.x - __bfloat162float(h0));
    __nv_bfloat16 l1 = __float2bfloat16(v.y - __bfloat162float(h1));
    __nv_bfloat16 l2 = __float2bfloat16(v.z - __bfloat162float(h2));
    __nv_bfloat16 l3 = __float2bfloat16(v.w - __bfloat162float(h3));
    *(__nv_bfloat162*)(hi + i)     = __nv_bfloat162(h0, h1);
    *(__nv_bfloat162*)(hi + i + 2) = __nv_bfloat162(h2, h3);
    *(__nv_bfloat162*)(lo + i)     = __nv_bfloat162(l0, l1);
    *(__nv_bfloat162*)(lo + i + 2) = __nv_bfloat162(l2, l3);
}

// ---------------------------------------------------------------------
// Tensor-core GEMM: C = (Ah+Al)[M,K] @ (Bh+Bl)[N,K]^T + bias[N]
// mode 0: C fp32; mode 1: (Ch, Cl) bf16 split output
// 2-stage cp.async pipeline, 2 CTAs/SM for cross-CTA latency hiding.
// ---------------------------------------------------------------------
#define STAGES 2
#define SSTAGE 40960
#define GEMM_SMEM (STAGES * SSTAGE)   // 81920 -> 2 CTAs/SM

__global__ __launch_bounds__(256, 2)
void gemm_mma(const __nv_bfloat16* __restrict__ Ah, const __nv_bfloat16* __restrict__ Al,
              const __nv_bfloat16* __restrict__ Bh, const __nv_bfloat16* __restrict__ Bl,
              const float* __restrict__ bias, float* __restrict__ C,
              __nv_bfloat16* __restrict__ Ch, __nv_bfloat16* __restrict__ Cl,
              int mode, int N, int K)
{
    extern __shared__ __align__(128) char smem[];
    const uint32_t sbase = smem_u32(smem);

    const int tid  = threadIdx.x;
    const int lane = tid & 31;
    const int wid  = tid >> 5;

    // banded CTA swizzle (L2-friendly; keep from R5)
    const int id    = blockIdx.y * gridDim.x + blockIdx.x;
    const int bandw = 8 * gridDim.x;
    const int band  = id / bandw;
    const int rem   = id - band * bandw;
    const int bm = (band * 8 + (rem & 7)) * 128;
    const int bn = (rem >> 3) * 128;

    const int wm = (wid >> 2) * 64;
    const int wn = (wid & 3) * 32;

    const uint32_t aoff = (uint32_t)((wm + (lane & 15)) * 80 + (lane >> 4) * 16);
    const uint32_t boff = (uint32_t)(20480 + (wn + (lane & 15)) * 80 + (lane >> 4) * 16);

    const __nv_bfloat16* Abase[2] = { Ah + (size_t)bm * K, Al + (size_t)bm * K };
    const __nv_bfloat16* Bbase[2] = { Bh + (size_t)bn * K, Bl + (size_t)bn * K };

    float c[4][4][4];
    #pragma unroll
    for (int i = 0; i < 4; i++)
        #pragma unroll
        for (int j = 0; j < 4; j++)
            #pragma unroll
            for (int q = 0; q < 4; q++) c[i][j][q] = 0.0f;

    const int nk = K >> 5;

    auto issue = [&](int kt, int slot) {
        const int koff = kt * 32;
        const uint32_t st = sbase + slot * SSTAGE;
        #pragma unroll
        for (int sp = 0; sp < 2; sp++) {
            #pragma unroll
            for (int it = 0; it < 2; it++) {
                int idx = tid + it * 256;
                int row = idx >> 2;
                int c16 = idx & 3;
                cp_async16(st + sp * 10240 + row * 80 + c16 * 16,
                           Abase[sp] + (size_t)row * K + koff + c16 * 8);
                cp_async16(st + 20480 + sp * 10240 + row * 80 + c16 * 16,
                           Bbase[sp] + (size_t)row * K + koff + c16 * 8);
            }
        }
    };

    issue(0, 0); cp_commit();

    for (int kt = 0; kt < nk; kt++) {
        cp_wait<0>();
        __syncthreads();   // stage kt ready; prior reads of the other slot done

        const int nxt = kt + 1;
        if (nxt < nk) { issue(nxt, nxt & 1); cp_commit(); }

        const uint32_t st = sbase + (kt & 1) * SSTAGE;
        #pragma unroll
        for (int kk = 0; kk < 2; kk++) {
            uint32_t ah[4][4], al[4][4], bh[2][4], bl[2][4];
            #pragma unroll
            for (int i = 0; i < 4; i++) {
                ldsm4(ah[i], st + aoff + i * 1280 + kk * 32);
                ldsm4(al[i], st + 10240 + aoff + i * 1280 + kk * 32);
            }
            #pragma unroll
            for (int j2 = 0; j2 < 2; j2++) {
                ldsm4(bh[j2], st + boff + j2 * 1280 + kk * 32);
                ldsm4(bl[j2], st + 10240 + boff + j2 * 1280 + kk * 32);
            }
            #pragma unroll
            for (int i = 0; i < 4; i++)
                #pragma unroll
                for (int j = 0; j < 4; j++) {
                    const int j2 = j >> 1, sl = j & 1;
                    mma16816(c[i][j], ah[i], bh[j2][sl], bh[j2][sl + 2]);
                    mma16816(c[i][j], ah[i], bl[j2][sl], bl[j2][sl + 2]);
                    mma16816(c[i][j], al[i], bh[j2][sl], bh[j2][sl + 2]);
                }
        }
        __syncthreads();   // all reads of this slot done before next overwrite
    }

    const int g = lane >> 2, t = lane & 3;
    #pragma unroll
    for (int j = 0; j < 4; j++) {
        const int col = bn + wn + j * 8 + t * 2;
        const float b0 = bias[col], b1 = bias[col + 1];
        #pragma unroll
        for (int i = 0; i < 4; i++) {
            const int row0 = bm + wm + i * 16 + g;
            float x0 = c[i][j][0] + b0, x1 = c[i][j][1] + b1;
            float x2 = c[i][j][2] + b0, x3 = c[i][j][3] + b1;
            if (mode == 0) {
                *(float2*)(C + (size_t)row0 * N + col)       = make_float2(x0, x1);
                *(float2*)(C + (size_t)(row0 + 8) * N + col) = make_float2(x2, x3);
            } else {
                __nv_bfloat16 h0 = __float2bfloat16(x0), h1 = __float2bfloat16(x1);
                __nv_bfloat16 h2 = __float2bfloat16(x2), h3 = __float2bfloat16(x3);
                *(__nv_bfloat162*)(Ch + (size_t)row0 * N + col) = __nv_bfloat162(h0, h1);
                *(__nv_bfloat162*)(Ch + (size_t)(row0 + 8) * N + col) = __nv_bfloat162(h2, h3);
                *(__nv_bfloat162*)(Cl + (size_t)row0 * N + col) =
                    __nv_bfloat162(__float2bfloat16(x0 - __bfloat162float(h0)),
                                   __float2bfloat16(x1 - __bfloat162float(h1)));
                *(__nv_bfloat162*)(Cl + (size_t)(row0 + 8) * N + col) =
                    __nv_bfloat162(__float2bfloat16(x2 - __bfloat162float(h2)),
                                   __float2bfloat16(x3 - __bfloat162float(h3)));
            }
        }
    }
}

// =====================================================================
// Tensorized flash attention (causal): Br=128, Bc=64, 8 warps
// =====================================================================
#define ASTR 272
#define QTILE (128 * ASTR)
#define KVTILE (64 * ASTR)
#define KVSTAGE (4 * KVTILE)
#define FLASH_SMEM (2 * QTILE + 2 * KVSTAGE)   // 208896

__global__ __launch_bounds__(256, 1)
void flash_attn_mma(const __nv_bfloat16* __restrict__ qkvh,
                    const __nv_bfloat16* __restrict__ qkvl,
                    __nv_bfloat16* __restrict__ ctxh,
                    __nv_bfloat16* __restrict__ ctxl)
{
    extern __shared__ __align__(128) char smem[];
    const uint32_t sb = smem_u32(smem);

    const int tid  = threadIdx.x;
    const int lane = tid & 31;
    const int wid  = tid >> 5;
    const int h  = blockIdx.y;
    const int qb = gridDim.x - 1 - blockIdx.x;
    const int q0w = qb * 128 + wid * 16;
    const int nkb = 2 * qb + 2;
    const float scale = 0.08838834764831845f;

    {
        const size_t qrow = (size_t)(qb * 128) * QKVC + h * HD;
        const __nv_bfloat16* qsrc[2] = { qkvh + qrow, qkvl + qrow };
        #pragma unroll
        for (int it = 0; it < 16; it++) {
            int idx = tid + it * 256;
            int sp = idx >> 11, rem = idx & 2047;
            int row = rem >> 4, ch = rem & 15;
            cp_async16(sb + sp * QTILE + row * ASTR + ch * 16,
                       qsrc[sp] + (size_t)row * QKVC + ch * 8);
        }
    }

    auto issueKV = [&](int kb, int slot) {
        const size_t roff = (size_t)(kb * 64) * QKVC + h * HD;
        const __nv_bfloat16* base[4] = { qkvh + EM + roff, qkvl + EM + roff,
                                         qkvh + 2 * EM + roff, qkvl + 2 * EM + roff };
        const uint32_t st = sb + 2 * QTILE + slot * KVSTAGE;
        #pragma unroll
        for (int it = 0; it < 16; it++) {
            int idx = tid + it * 256;
            int arr = idx >> 10, rem = idx & 1023;
            int row = rem >> 4, ch = rem & 15;
            cp_async16(st + arr * KVTILE + row * ASTR + ch * 16,
                       base[arr] + (size_t)row * QKVC + ch * 8);
        }
    };

    issueKV(0, 0); cp_commit();
    issueKV(1, 1); cp_commit();

    float m[2] = { -1e30f, -1e30f };
    float l[2] = { 0.0f, 0.0f };
    float o[16][4];
    #pragma unroll
    for (int n = 0; n < 16; n++)
        #pragma unroll
        for (int q = 0; q < 4; q++) o[n][q] = 0.0f;

    const int g = lane >> 2, t = lane & 3;
    const uint32_t qaddr = sb + (wid * 16 + (lane & 15)) * ASTR + (lane >> 4) * 16;
    const uint32_t kvlane = (uint32_t)((lane & 15) * ASTR + (lane >> 4) * 16);

    for (int kb = 0; kb < nkb; kb++) {
        cp_wait<1>();
        __syncthreads();

        const int slot = kb & 1;
        const uint32_t kB = sb + 2 * QTILE + slot * KVSTAGE;
        const uint32_t vB = kB + 2 * KVTILE;
        const bool skip = (kb * 64 > q0w + 15);

        if (!skip) {
            float s[8][4];
            #pragma unroll
            for (int j = 0; j < 8; j++)
                #pragma unroll
                for (int q = 0; q < 4; q++) s[j][q] = 0.0f;

            #pragma unroll
            for (int ks = 0; ks < 8; ks++) {
                uint32_t ah4[4], al4[4];
                ldsm4(ah4, qaddr + ks * 32);
                ldsm4(al4, qaddr + QTILE + ks * 32);
                #pragma unroll
                for (int p2 = 0; p2 < 4; p2++) {
                    uint32_t bh4[4], bl4[4];
                    ldsm4(bh4, kB + kvlane + p2 * (16 * ASTR) + ks * 32);
                    ldsm4(bl4, kB + KVTILE + kvlane + p2 * (16 * ASTR) + ks * 32);
                    #pragma unroll
                    for (int sl = 0; sl < 2; sl++) {
                        const int j = p2 * 2 + sl;
                        mma16816(s[j], ah4, bh4[sl], bh4[sl + 2]);
                        mma16816(s[j], ah4, bl4[sl], bl4[sl + 2]);
                        mma16816(s[j], al4, bh4[sl], bh4[sl + 2]);
                    }
                }
            }

            const bool dm = (kb * 64 + 63 > q0w);
            const int r0 = q0w + g, r1 = q0w + 8 + g;
            float mx0 = -1e30f, mx1 = -1e30f;
            #pragma unroll
            for (int j = 0; j < 8; j++) {
                const int col = kb * 64 + 8 * j + 2 * t;
                float v0 = s[j][0] * scale, v1 = s[j][1] * scale;
                float v2 = s[j][2] * scale, v3 = s[j][3] * scale;
                if (dm) {
                    if (col     > r0) v0 = -1e30f;
                    if (col + 1 > r0) v1 = -1e30f;
                    if (col     > r1) v2 = -1e30f;
                    if (col + 1 > r1) v3 = -1e30f;
                }
                s[j][0] = v0; s[j][1] = v1; s[j][2] = v2; s[j][3] = v3;
                mx0 = fmaxf(mx0, fmaxf(v0, v1));
                mx1 = fmaxf(mx1, fmaxf(v2, v3));
            }
            mx0 = fmaxf(mx0, __shfl_xor_sync(0xffffffffu, mx0, 1));
            mx0 = fmaxf(mx0, __shfl_xor_sync(0xffffffffu, mx0, 2));
            mx1 = fmaxf(mx1, __shfl_xor_sync(0xffffffffu, mx1, 1));
            mx1 = fmaxf(mx1, __shfl_xor_sync(0xffffffffu, mx1, 2));

            const float mn0 = fmaxf(m[0], mx0);
            const float mn1 = fmaxf(m[1], mx1);
            float rs0 = 0.0f, rs1 = 0.0f;
            #pragma unroll
            for (int j = 0; j < 8; j++) {
                s[j][0] = __expf(s[j][0] - mn0);
                s[j][1] = __expf(s[j][1] - mn0);
                s[j][2] = __expf(s[j][2] - mn1);
                s[j][3] = __expf(s[j][3] - mn1);
                rs0 += s[j][0] + s[j][1];
                rs1 += s[j][2] + s[j][3];
            }
            rs0 += __shfl_xor_sync(0xffffffffu, rs0, 1);
            rs0 += __shfl_xor_sync(0xffffffffu, rs0, 2);
            rs1 += __shfl_xor_sync(0xffffffffu, rs1, 1);
            rs1 += __shfl_xor_sync(0xffffffffu, rs1, 2);

            const float f0 = __expf(m[0] - mn0);
            const float f1 = __expf(m[1] - mn1);
            l[0] = l[0] * f0 + rs0; l[1] = l[1] * f1 + rs1;
            m[0] = mn0; m[1] = mn1;
            #pragma unroll
            for (int n = 0; n < 16; n++) {
                o[n][0] *= f0; o[n][1] *= f0;
                o[n][2] *= f1; o[n][3] *= f1;
            }

            #pragma unroll
            for (int jp = 0; jp < 4; jp++) {
                uint32_t ph[4], pl[4];
                {
                    const float* p0 = s[2 * jp];
                    const float* p1 = s[2 * jp + 1];
                    ph[0] = pack_bf16(p0[0], p0[1]);
                    ph[1] = pack_bf16(p0[2], p0[3]);
                    ph[2] = pack_bf16(p1[0], p1[1]);
                    ph[3] = pack_bf16(p1[2], p1[3]);
                    __nv_bfloat162* hp;
                    hp = (__nv_bfloat162*)&ph[0];
                    pl[0] = pack_bf16(p0[0] - __bfloat162float(hp->x), p0[1] - __bfloat162float(hp->y));
                    hp = (__nv_bfloat162*)&ph[1];
                    pl[1] = pack_bf16(p0[2] - __bfloat162float(hp->x), p0[3] - __bfloat162float(hp->y));
                    hp = (__nv_bfloat162*)&ph[2];
                    pl[2] = pack_bf16(p1[0] - __bfloat162float(hp->x), p1[1] - __bfloat162float(hp->y));
                    hp = (__nv_bfloat162*)&ph[3];
                    pl[3] = pack_bf16(p1[2] - __bfloat162float(hp->x), p1[3] - __bfloat162float(hp->y));
                }
                #pragma unroll
                for (int np = 0; np < 8; np++) {
                    uint32_t bh4[4], bl4[4];
                    ldsm4t(bh4, vB + kvlane + jp * (16 * ASTR) + np * 32);
                    ldsm4t(bl4, vB + KVTILE + kvlane + jp * (16 * ASTR) + np * 32);
                    mma16816(o[2 * np],     ph, bh4[0], bh4[1]);
                    mma16816(o[2 * np],     ph, bl4[0], bl4[1]);
                    mma16816(o[2 * np],     pl, bh4[0], bh4[1]);
                    mma16816(o[2 * np + 1], ph, bh4[2], bh4[3]);
                    mma16816(o[2 * np + 1], ph, bl4[2], bl4[3]);
                    mma16816(o[2 * np + 1], pl, bh4[2], bh4[3]);
                }
            }
        }

        __syncthreads();
        if (kb + 2 < nkb) issueKV(kb + 2, slot);
        cp_commit();
    }

    const float inv0 = 1.0f / l[0];
    const float inv1 = 1.0f / l[1];
    const int r0 = q0w + g, r1 = q0w + 8 + g;
    #pragma unroll
    for (int n = 0; n < 16; n++) {
        const int col = h * HD + n * 8 + 2 * t;
        float x0 = o[n][0] * inv0, x1 = o[n][1] * inv0;
        float x2 = o[n][2] * inv1, x3 = o[n][3] * inv1;
        __nv_bfloat16 h0 = __float2bfloat16(x0), h1 = __float2bfloat16(x1);
        __nv_bfloat16 h2 = __float2bfloat16(x2), h3 = __float2bfloat16(x3);
        *(__nv_bfloat162*)(ctxh + (size_t)r0 * EM + col) = __nv_bfloat162(h0, h1);
        *(__nv_bfloat162*)(ctxh + (size_t)r1 * EM + col) = __nv_bfloat162(h2, h3);
        *(__nv_bfloat162*)(ctxl + (size_t)r0 * EM + col) =
            __nv_bfloat162(__float2bfloat16(x0 - __bfloat162float(h0)),
                           __float2bfloat16(x1 - __bfloat162float(h1)));
        *(__nv_bfloat162*)(ctxl + (size_t)r1 * EM + col) =
            __nv_bfloat162(__float2bfloat16(x2 - __bfloat162float(h2)),
                           __float2bfloat16(x3 - __bfloat162float(h3)));
    }
}

// =====================================================================
extern "C" void kernel_launch(void* const* d_in, const int* in_sizes, int n_in,
                              void* d_out, int out_size)
{
    (void)in_sizes; (void)n_in; (void)out_size;
    const float* hs   = (const float*)d_in[0];
    const float* wqkv = (const float*)d_in[1];
    const float* bqkv = (const float*)d_in[2];
    const float* wo   = (const float*)d_in[3];
    const float* bo   = (const float*)d_in[4];
    float* out = (float*)d_out;

    __nv_bfloat16 *qkvh, *qkvl, *ah, *al, *bh, *bl;
    cudaGetSymbolAddress((void**)&qkvh, g_qkvh);
    cudaGetSymbolAddress((void**)&qkvl, g_qkvl);
    cudaGetSymbolAddress((void**)&ah, g_ah);
    cudaGetSymbolAddress((void**)&al, g_al);
    cudaGetSymbolAddress((void**)&bh, g_bh);
    cudaGetSymbolAddress((void**)&bl, g_bl);

    cudaFuncSetAttribute(gemm_mma, cudaFuncAttributeMaxDynamicSharedMemorySize, GEMM_SMEM);
    cudaFuncSetAttribute(flash_attn_mma, cudaFuncAttributeMaxDynamicSharedMemorySize, FLASH_SMEM);

    // 1) splits for QKV projection
    split_bf16<<<(SQ * EM / 4 + 255) / 256, 256>>>(hs, ah, al, SQ * EM);
    split_bf16<<<(QKVC * EM / 4 + 255) / 256, 256>>>(wqkv, bh, bl, QKVC * EM);

    // 2) QKV projection -> bf16 split output (fused)
    dim3 g1(QKVC / 128, SQ / 128);
    gemm_mma<<<g1, 256, GEMM_SMEM>>>(ah, al, bh, bl, bqkv, nullptr, qkvh, qkvl, 1, QKVC, EM);

    // 3) split Wo
    split_bf16<<<(EM * EM / 4 + 255) / 256, 256>>>(wo, bh, bl, EM * EM);

    // 4) tensorized causal flash attention -> ctx as bf16 split
    dim3 g2(SQ / 128, NH);
    flash_attn_mma<<<g2, 256, FLASH_SMEM>>>(qkvh, qkvl, ah, al);

    // 5) output projection -> fp32 out
    dim3 g3(EM / 128, SQ / 128);
    gemm_mma<<<g3, 256, GEMM_SMEM>>>(ah, al, bh, bl, bo, out, nullptr, nullptr, 0, EM, EM);
}

// round 7
// speedup vs baseline: 3.7479x; 1.4300x over previous
#include <cuda_runtime.h>
#include <cuda_fp16.h>
#include <math.h>
#include <cstdint>

#define SQ   4096
#define EM   2048
#define NH   16
#define HD   128
#define QKVC (3*EM)

// ---------------------------------------------------------------------
// Scratch (allocation-free rule: device globals)
// ---------------------------------------------------------------------
__device__ __half g_qkvh[(size_t)SQ * QKVC];   // qkv hi split
__device__ __half g_qkvl[(size_t)SQ * QKVC];   // qkv lo split (only Q-lo consumed)
__device__ __half g_ah[(size_t)SQ * EM];       // A hi (hs, then ctx)
__device__ __half g_al[(size_t)SQ * EM];       // A lo
__device__ __half g_bh[(size_t)QKVC * EM];     // W hi (Wqkv, then Wo) — 11-bit operand

// ---------------------------------------------------------------------
// Portable PTX helpers
// ---------------------------------------------------------------------
__device__ __forceinline__ uint32_t smem_u32(const void* p) {
    uint32_t a;
    asm("{ .reg .u64 t; cvta.to.shared.u64 t, %1; cvt.u32.u64 %0, t; }" : "=r"(a) : "l"(p));
    return a;
}
__device__ __forceinline__ void cp_async16(uint32_t saddr, const void* gaddr) {
    asm volatile("cp.async.cg.shared.global [%0], [%1], 16;" :: "r"(saddr), "l"(gaddr));
}
__device__ __forceinline__ void cp_commit() { asm volatile("cp.async.commit_group;"); }
template <int N>
__device__ __forceinline__ void cp_wait() { asm volatile("cp.async.wait_group %0;" :: "n"(N)); }

__device__ __forceinline__ void ldsm4(uint32_t* r, uint32_t addr) {
    asm volatile("ldmatrix.sync.aligned.m8n8.x4.shared.b16 {%0,%1,%2,%3}, [%4];"
        : "=r"(r[0]), "=r"(r[1]), "=r"(r[2]), "=r"(r[3]) : "r"(addr));
}
__device__ __forceinline__ void ldsm4t(uint32_t* r, uint32_t addr) {
    asm volatile("ldmatrix.sync.aligned.m8n8.x4.trans.shared.b16 {%0,%1,%2,%3}, [%4];"
        : "=r"(r[0]), "=r"(r[1]), "=r"(r[2]), "=r"(r[3]) : "r"(addr));
}
// fp16 inputs, fp32 accumulate
__device__ __forceinline__ void mma16816(float* c, const uint32_t* a, uint32_t b0, uint32_t b1) {
    asm volatile("mma.sync.aligned.m16n8k16.row.col.f32.f16.f16.f32 "
        "{%0,%1,%2,%3}, {%4,%5,%6,%7}, {%8,%9}, {%0,%1,%2,%3};"
        : "+f"(c[0]), "+f"(c[1]), "+f"(c[2]), "+f"(c[3])
        : "r"(a[0]), "r"(a[1]), "r"(a[2]), "r"(a[3]), "r"(b0), "r"(b1));
}
__device__ __forceinline__ uint32_t pack_h2(float a, float b) {
    __half2 v = __floats2half2_rn(a, b);
    return *reinterpret_cast<uint32_t*>(&v);
}

// ---------------------------------------------------------------------
// Split fp32 -> (hi fp16, lo fp16)
// ---------------------------------------------------------------------
__global__ __launch_bounds__(256)
void split_f16(const float* __restrict__ x, __half* __restrict__ hi,
               __half* __restrict__ lo, int n)
{
    int i = (blockIdx.x * 256 + threadIdx.x) * 4;
    if (i >= n) return;
    float4 v = *(const float4*)(x + i);
    __half h0 = __float2half_rn(v.x), h1 = __float2half_rn(v.y);
    __half h2 = __float2half_rn(v.z), h3 = __float2half_rn(v.w);
    __half l0 = __float2half_rn(v.x - __half2float(h0));
    __half l1 = __float2half_rn(v.y - __half2float(h1));
    __half l2 = __float2half_rn(v.z - __half2float(h2));
    __half l3 = __float2half_rn(v.w - __half2float(h3));
    *(__half2*)(hi + i)     = __halves2half2(h0, h1);
    *(__half2*)(hi + i + 2) = __halves2half2(h2, h3);
    *(__half2*)(lo + i)     = __halves2half2(l0, l1);
    *(__half2*)(lo + i + 2) = __halves2half2(l2, l3);
}

// Convert fp32 -> fp16 (hi only, for the 11-bit weight operand)
__global__ __launch_bounds__(256)
void conv_f16(const float* __restrict__ x, __half* __restrict__ hi, int n)
{
    int i = (blockIdx.x * 256 + threadIdx.x) * 4;
    if (i >= n) return;
    float4 v = *(const float4*)(x + i);
    *(__half2*)(hi + i)     = __floats2half2_rn(v.x, v.y);
    *(__half2*)(hi + i + 2) = __floats2half2_rn(v.z, v.w);
}

// ---------------------------------------------------------------------
// Tensor-core GEMM: C = (Ah+Al)[M,K] @ Bh[N,K]^T + bias[N]   (2 products)
// mode 0: C fp32; mode 1: (Ch, Cl) fp16 split output
// 2-stage cp.async pipeline, 2 CTAs/SM.
// ---------------------------------------------------------------------
#define STAGES 2
#define SSTAGE 30720          // A hi 10240 + A lo 10240 + B hi 10240
#define GEMM_SMEM (STAGES * SSTAGE)   // 61440 -> 2 CTAs/SM

__global__ __launch_bounds__(256, 2)
void gemm_mma(const __half* __restrict__ Ah, const __half* __restrict__ Al,
              const __half* __restrict__ Bh,
              const float* __restrict__ bias, float* __restrict__ C,
              __half* __restrict__ Ch, __half* __restrict__ Cl,
              int mode, int N, int K)
{
    extern __shared__ __align__(128) char smem[];
    const uint32_t sbase = smem_u32(smem);

    const int tid  = threadIdx.x;
    const int lane = tid & 31;
    const int wid  = tid >> 5;

    // banded CTA swizzle (L2-friendly)
    const int id    = blockIdx.y * gridDim.x + blockIdx.x;
    const int bandw = 8 * gridDim.x;
    const int band  = id / bandw;
    const int rem   = id - band * bandw;
    const int bm = (band * 8 + (rem & 7)) * 128;
    const int bn = (rem >> 3) * 128;

    const int wm = (wid >> 2) * 64;
    const int wn = (wid & 3) * 32;

    const uint32_t aoff = (uint32_t)((wm + (lane & 15)) * 80 + (lane >> 4) * 16);
    const uint32_t boff = (uint32_t)(20480 + (wn + (lane & 15)) * 80 + (lane >> 4) * 16);

    const __half* Abase[2] = { Ah + (size_t)bm * K, Al + (size_t)bm * K };
    const __half* Bbase    =   Bh + (size_t)bn * K;

    float c[4][4][4];
    #pragma unroll
    for (int i = 0; i < 4; i++)
        #pragma unroll
        for (int j = 0; j < 4; j++)
            #pragma unroll
            for (int q = 0; q < 4; q++) c[i][j][q] = 0.0f;

    const int nk = K >> 5;

    auto issue = [&](int kt, int slot) {
        const int koff = kt * 32;
        const uint32_t st = sbase + slot * SSTAGE;
        #pragma unroll
        for (int sp = 0; sp < 2; sp++) {
            #pragma unroll
            for (int it = 0; it < 2; it++) {
                int idx = tid + it * 256;
                int row = idx >> 2;
                int c16 = idx & 3;
                cp_async16(st + sp * 10240 + row * 80 + c16 * 16,
                           Abase[sp] + (size_t)row * K + koff + c16 * 8);
            }
        }
        #pragma unroll
        for (int it = 0; it < 2; it++) {
            int idx = tid + it * 256;
            int row = idx >> 2;
            int c16 = idx & 3;
            cp_async16(st + 20480 + row * 80 + c16 * 16,
                       Bbase + (size_t)row * K + koff + c16 * 8);
        }
    };

    issue(0, 0); cp_commit();

    for (int kt = 0; kt < nk; kt++) {
        cp_wait<0>();
        __syncthreads();

        const int nxt = kt + 1;
        if (nxt < nk) { issue(nxt, nxt & 1); cp_commit(); }

        const uint32_t st = sbase + (kt & 1) * SSTAGE;
        #pragma unroll
        for (int kk = 0; kk < 2; kk++) {
            uint32_t ah[4][4], al[4][4], bh[2][4];
            #pragma unroll
            for (int i = 0; i < 4; i++) {
                ldsm4(ah[i], st + aoff + i * 1280 + kk * 32);
                ldsm4(al[i], st + 10240 + aoff + i * 1280 + kk * 32);
            }
            #pragma unroll
            for (int j2 = 0; j2 < 2; j2++)
                ldsm4(bh[j2], st + boff + j2 * 1280 + kk * 32);
            #pragma unroll
            for (int i = 0; i < 4; i++)
                #pragma unroll
                for (int j = 0; j < 4; j++) {
                    const int j2 = j >> 1, sl = j & 1;
                    mma16816(c[i][j], ah[i], bh[j2][sl], bh[j2][sl + 2]);
                    mma16816(c[i][j], al[i], bh[j2][sl], bh[j2][sl + 2]);
                }
        }
        __syncthreads();
    }

    const int g = lane >> 2, t = lane & 3;
    #pragma unroll
    for (int j = 0; j < 4; j++) {
        const int col = bn + wn + j * 8 + t * 2;
        const float b0 = bias[col], b1 = bias[col + 1];
        #pragma unroll
        for (int i = 0; i < 4; i++) {
            const int row0 = bm + wm + i * 16 + g;
            float x0 = c[i][j][0] + b0, x1 = c[i][j][1] + b1;
            float x2 = c[i][j][2] + b0, x3 = c[i][j][3] + b1;
            if (mode == 0) {
                *(float2*)(C + (size_t)row0 * N + col)       = make_float2(x0, x1);
                *(float2*)(C + (size_t)(row0 + 8) * N + col) = make_float2(x2, x3);
            } else {
                __half h0 = __float2half_rn(x0), h1 = __float2half_rn(x1);
                __half h2 = __float2half_rn(x2), h3 = __float2half_rn(x3);
                *(__half2*)(Ch + (size_t)row0 * N + col)       = __halves2half2(h0, h1);
                *(__half2*)(Ch + (size_t)(row0 + 8) * N + col) = __halves2half2(h2, h3);
                *(__half2*)(Cl + (size_t)row0 * N + col) =
                    __halves2half2(__float2half_rn(x0 - __half2float(h0)),
                                   __float2half_rn(x1 - __half2float(h1)));
                *(__half2*)(Cl + (size_t)(row0 + 8) * N + col) =
                    __halves2half2(__float2half_rn(x2 - __half2float(h2)),
                                   __float2half_rn(x3 - __half2float(h3)));
            }
        }
    }
}

// =====================================================================
// Tensorized flash attention (causal): Br=128, Bc=64, 8 warps
// QK: Qh/Ql (22b) x Kh (11b) — 2 products. PV: Ph/Pl x Vh — 2 products.
// =====================================================================
#define ASTR 272
#define QTILE (128 * ASTR)             // 34816
#define KVTILE (64 * ASTR)             // 17408
#define KVSTAGE (2 * KVTILE)           // Kh + Vh = 34816
#define FLASH_SMEM (2 * QTILE + 2 * KVSTAGE)   // 139264

__global__ __launch_bounds__(256, 1)
void flash_attn_mma(const __half* __restrict__ qkvh,
                    const __half* __restrict__ qkvl,
                    __half* __restrict__ ctxh,
                    __half* __restrict__ ctxl)
{
    extern __shared__ __align__(128) char smem[];
    const uint32_t sb = smem_u32(smem);

    const int tid  = threadIdx.x;
    const int lane = tid & 31;
    const int wid  = tid >> 5;
    const int h  = blockIdx.y;
    const int qb = gridDim.x - 1 - blockIdx.x;
    const int q0w = qb * 128 + wid * 16;
    const int nkb = 2 * qb + 2;
    const float scale = 0.08838834764831845f;

    {
        const size_t qrow = (size_t)(qb * 128) * QKVC + h * HD;
        const __half* qsrc[2] = { qkvh + qrow, qkvl + qrow };
        #pragma unroll
        for (int it = 0; it < 16; it++) {
            int idx = tid + it * 256;
            int sp = idx >> 11, rem = idx & 2047;
            int row = rem >> 4, ch = rem & 15;
            cp_async16(sb + sp * QTILE + row * ASTR + ch * 16,
                       qsrc[sp] + (size_t)row * QKVC + ch * 8);
        }
    }

    auto issueKV = [&](int kb, int slot) {
        const size_t roff = (size_t)(kb * 64) * QKVC + h * HD;
        const __half* base[2] = { qkvh + EM + roff, qkvh + 2 * EM + roff };
        const uint32_t st = sb + 2 * QTILE + slot * KVSTAGE;
        #pragma unroll
        for (int it = 0; it < 8; it++) {
            int idx = tid + it * 256;
            int arr = idx >> 10, rem = idx & 1023;
            int row = rem >> 4, ch = rem & 15;
            cp_async16(st + arr * KVTILE + row * ASTR + ch * 16,
                       base[arr] + (size_t)row * QKVC + ch * 8);
        }
    };

    issueKV(0, 0); cp_commit();
    issueKV(1, 1); cp_commit();

    float m[2] = { -1e30f, -1e30f };
    float l[2] = { 0.0f, 0.0f };
    float o[16][4];
    #pragma unroll
    for (int n = 0; n < 16; n++)
        #pragma unroll
        for (int q = 0; q < 4; q++) o[n][q] = 0.0f;

    const int g = lane >> 2, t = lane & 3;
    const uint32_t qaddr = sb + (wid * 16 + (lane & 15)) * ASTR + (lane >> 4) * 16;
    const uint32_t kvlane = (uint32_t)((lane & 15) * ASTR + (lane >> 4) * 16);

    for (int kb = 0; kb < nkb; kb++) {
        cp_wait<1>();
        __syncthreads();

        const int slot = kb & 1;
        const uint32_t kB = sb + 2 * QTILE + slot * KVSTAGE;
        const uint32_t vB = kB + KVTILE;
        const bool skip = (kb * 64 > q0w + 15);

        if (!skip) {
            float s[8][4];
            #pragma unroll
            for (int j = 0; j < 8; j++)
                #pragma unroll
                for (int q = 0; q < 4; q++) s[j][q] = 0.0f;

            #pragma unroll
            for (int ks = 0; ks < 8; ks++) {
                uint32_t ah4[4], al4[4];
                ldsm4(ah4, qaddr + ks * 32);
                ldsm4(al4, qaddr + QTILE + ks * 32);
                #pragma unroll
                for (int p2 = 0; p2 < 4; p2++) {
                    uint32_t bh4[4];
                    ldsm4(bh4, kB + kvlane + p2 * (16 * ASTR) + ks * 32);
                    #pragma unroll
                    for (int sl = 0; sl < 2; sl++) {
                        const int j = p2 * 2 + sl;
                        mma16816(s[j], ah4, bh4[sl], bh4[sl + 2]);
                        mma16816(s[j], al4, bh4[sl], bh4[sl + 2]);
                    }
                }
            }

            const bool dm = (kb * 64 + 63 > q0w);
            const int r0 = q0w + g, r1 = q0w + 8 + g;
            float mx0 = -1e30f, mx1 = -1e30f;
            #pragma unroll
            for (int j = 0; j < 8; j++) {
                const int col = kb * 64 + 8 * j + 2 * t;
                float v0 = s[j][0] * scale, v1 = s[j][1] * scale;
                float v2 = s[j][2] * scale, v3 = s[j][3] * scale;
                if (dm) {
                    if (col     > r0) v0 = -1e30f;
                    if (col + 1 > r0) v1 = -1e30f;
                    if (col     > r1) v2 = -1e30f;
                    if (col + 1 > r1) v3 = -1e30f;
                }
                s[j][0] = v0; s[j][1] = v1; s[j][2] = v2; s[j][3] = v3;
                mx0 = fmaxf(mx0, fmaxf(v0, v1));
                mx1 = fmaxf(mx1, fmaxf(v2, v3));
            }
            mx0 = fmaxf(mx0, __shfl_xor_sync(0xffffffffu, mx0, 1));
            mx0 = fmaxf(mx0, __shfl_xor_sync(0xffffffffu, mx0, 2));
            mx1 = fmaxf(mx1, __shfl_xor_sync(0xffffffffu, mx1, 1));
            mx1 = fmaxf(mx1, __shfl_xor_sync(0xffffffffu, mx1, 2));

            const float mn0 = fmaxf(m[0], mx0);
            const float mn1 = fmaxf(m[1], mx1);
            float rs0 = 0.0f, rs1 = 0.0f;
            #pragma unroll
            for (int j = 0; j < 8; j++) {
                s[j][0] = __expf(s[j][0] - mn0);
                s[j][1] = __expf(s[j][1] - mn0);
                s[j][2] = __expf(s[j][2] - mn1);
                s[j][3] = __expf(s[j][3] - mn1);
                rs0 += s[j][0] + s[j][1];
                rs1 += s[j][2] + s[j][3];
            }
            rs0 += __shfl_xor_sync(0xffffffffu, rs0, 1);
            rs0 += __shfl_xor_sync(0xffffffffu, rs0, 2);
            rs1 += __shfl_xor_sync(0xffffffffu, rs1, 1);
            rs1 += __shfl_xor_sync(0xffffffffu, rs1, 2);

            const float f0 = __expf(m[0] - mn0);
            const float f1 = __expf(m[1] - mn1);
            l[0] = l[0] * f0 + rs0; l[1] = l[1] * f1 + rs1;
            m[0] = mn0; m[1] = mn1;
            #pragma unroll
            for (int n = 0; n < 16; n++) {
                o[n][0] *= f0; o[n][1] *= f0;
                o[n][2] *= f1; o[n][3] *= f1;
            }

            #pragma unroll
            for (int jp = 0; jp < 4; jp++) {
                uint32_t ph[4], pl[4];
                {
                    const float* p0 = s[2 * jp];
                    const float* p1 = s[2 * jp + 1];
                    ph[0] = pack_h2(p0[0], p0[1]);
                    ph[1] = pack_h2(p0[2], p0[3]);
                    ph[2] = pack_h2(p1[0], p1[1]);
                    ph[3] = pack_h2(p1[2], p1[3]);
                    __half2* hp;
                    hp = (__half2*)&ph[0];
                    pl[0] = pack_h2(p0[0] - __half2float(hp->x), p0[1] - __half2float(hp->y));
                    hp = (__half2*)&ph[1];
                    pl[1] = pack_h2(p0[2] - __half2float(hp->x), p0[3] - __half2float(hp->y));
                    hp = (__half2*)&ph[2];
                    pl[2] = pack_h2(p1[0] - __half2float(hp->x), p1[1] - __half2float(hp->y));
                    hp = (__half2*)&ph[3];
                    pl[3] = pack_h2(p1[2] - __half2float(hp->x), p1[3] - __half2float(hp->y));
                }
                #pragma unroll
                for (int np = 0; np < 8; np++) {
                    uint32_t bh4[4];
                    ldsm4t(bh4, vB + kvlane + jp * (16 * ASTR) + np * 32);
                    mma16816(o[2 * np],     ph, bh4[0], bh4[1]);
                    mma16816(o[2 * np],     pl, bh4[0], bh4[1]);
                    mma16816(o[2 * np + 1], ph, bh4[2], bh4[3]);
                    mma16816(o[2 * np + 1], pl, bh4[2], bh4[3]);
                }
            }
        }

        __syncthreads();
        if (kb + 2 < nkb) issueKV(kb + 2, slot);
        cp_commit();
    }

    const float inv0 = 1.0f / l[0];
    const float inv1 = 1.0f / l[1];
    const int r0 = q0w + g, r1 = q0w + 8 + g;
    #pragma unroll
    for (int n = 0; n < 16; n++) {
        const int col = h * HD + n * 8 + 2 * t;
        float x0 = o[n][0] * inv0, x1 = o[n][1] * inv0;
        float x2 = o[n][2] * inv1, x3 = o[n][3] * inv1;
        __half h0 = __float2half_rn(x0), h1 = __float2half_rn(x1);
        __half h2 = __float2half_rn(x2), h3 = __float2half_rn(x3);
        *(__half2*)(ctxh + (size_t)r0 * EM + col) = __halves2half2(h0, h1);
        *(__half2*)(ctxh + (size_t)r1 * EM + col) = __halves2half2(h2, h3);
        *(__half2*)(ctxl + (size_t)r0 * EM + col) =
            __halves2half2(__float2half_rn(x0 - __half2float(h0)),
                           __float2half_rn(x1 - __half2float(h1)));
        *(__half2*)(ctxl + (size_t)r1 * EM + col) =
            __halves2half2(__float2half_rn(x2 - __half2float(h2)),
                           __float2half_rn(x3 - __half2float(h3)));
    }
}

// =====================================================================
extern "C" void kernel_launch(void* const* d_in, const int* in_sizes, int n_in,
                              void* d_out, int out_size)
{
    (void)in_sizes; (void)n_in; (void)out_size;
    const float* hs   = (const float*)d_in[0];
    const float* wqkv = (const float*)d_in[1];
    const float* bqkv = (const float*)d_in[2];
    const float* wo   = (const float*)d_in[3];
    const float* bo   = (const float*)d_in[4];
    float* out = (float*)d_out;

    __half *qkvh, *qkvl, *ah, *al, *bh;
    cudaGetSymbolAddress((void**)&qkvh, g_qkvh);
    cudaGetSymbolAddress((void**)&qkvl, g_qkvl);
    cudaGetSymbolAddress((void**)&ah, g_ah);
    cudaGetSymbolAddress((void**)&al, g_al);
    cudaGetSymbolAddress((void**)&bh, g_bh);

    cudaFuncSetAttribute(gemm_mma, cudaFuncAttributeMaxDynamicSharedMemorySize, GEMM_SMEM);
    cudaFuncSetAttribute(flash_attn_mma, cudaFuncAttributeMaxDynamicSharedMemorySize, FLASH_SMEM);

    // 1) split hs (22-bit A operand); convert Wqkv (11-bit B operand)
    split_f16<<<(SQ * EM / 4 + 255) / 256, 256>>>(hs, ah, al, SQ * EM);
    conv_f16<<<(QKVC * EM / 4 + 255) / 256, 256>>>(wqkv, bh, QKVC * EM);

    // 2) QKV projection -> fp16 split output
    dim3 g1(QKVC / 128, SQ / 128);
    gemm_mma<<<g1, 256, GEMM_SMEM>>>(ah, al, bh, bqkv, nullptr, qkvh, qkvl, 1, QKVC, EM);

    // 3) convert Wo (stream-ordered after gemm1's reads of bh)
    conv_f16<<<(EM * EM / 4 + 255) / 256, 256>>>(wo, bh, EM * EM);

    // 4) causal flash attention -> ctx as fp16 split (overwrites ah/al)
    dim3 g2(SQ / 128, NH);
    flash_attn_mma<<<g2, 256, FLASH_SMEM>>>(qkvh, qkvl, ah, al);

    // 5) output projection -> fp32 out
    dim3 g3(EM / 128, SQ / 128);
    gemm_mma<<<g3, 256, GEMM_SMEM>>>(ah, al, bh, bo, out, nullptr, nullptr, 0, EM, EM);
}

// round 8
// speedup vs baseline: 5.6795x; 1.5154x over previous
#include <cuda_runtime.h>
#include <cuda_fp16.h>
#include <math.h>
#include <cstdint>

#define SQ   4096
#define EM   2048
#define NH   16
#define HD   128
#define QKVC (3*EM)

// ---------------------------------------------------------------------
// Scratch (allocation-free rule: device globals)
// ---------------------------------------------------------------------
__device__ __half g_qkvh[(size_t)SQ * QKVC];   // qkv (fp16)
__device__ __half g_ah[(size_t)SQ * EM];       // A (hs, then ctx) fp16
__device__ __half g_bh[(size_t)QKVC * EM];     // W (Wqkv, then Wo) fp16

// ---------------------------------------------------------------------
// Portable PTX helpers
// ---------------------------------------------------------------------
__device__ __forceinline__ uint32_t smem_u32(const void* p) {
    uint32_t a;
    asm("{ .reg .u64 t; cvta.to.shared.u64 t, %1; cvt.u32.u64 %0, t; }" : "=r"(a) : "l"(p));
    return a;
}
__device__ __forceinline__ void cp_async16(uint32_t saddr, const void* gaddr) {
    asm volatile("cp.async.cg.shared.global [%0], [%1], 16;" :: "r"(saddr), "l"(gaddr));
}
__device__ __forceinline__ void cp_commit() { asm volatile("cp.async.commit_group;"); }
template <int N>
__device__ __forceinline__ void cp_wait() { asm volatile("cp.async.wait_group %0;" :: "n"(N)); }

__device__ __forceinline__ void ldsm4(uint32_t* r, uint32_t addr) {
    asm volatile("ldmatrix.sync.aligned.m8n8.x4.shared.b16 {%0,%1,%2,%3}, [%4];"
        : "=r"(r[0]), "=r"(r[1]), "=r"(r[2]), "=r"(r[3]) : "r"(addr));
}
__device__ __forceinline__ void ldsm4t(uint32_t* r, uint32_t addr) {
    asm volatile("ldmatrix.sync.aligned.m8n8.x4.trans.shared.b16 {%0,%1,%2,%3}, [%4];"
        : "=r"(r[0]), "=r"(r[1]), "=r"(r[2]), "=r"(r[3]) : "r"(addr));
}
__device__ __forceinline__ void mma16816(float* c, const uint32_t* a, uint32_t b0, uint32_t b1) {
    asm volatile("mma.sync.aligned.m16n8k16.row.col.f32.f16.f16.f32 "
        "{%0,%1,%2,%3}, {%4,%5,%6,%7}, {%8,%9}, {%0,%1,%2,%3};"
        : "+f"(c[0]), "+f"(c[1]), "+f"(c[2]), "+f"(c[3])
        : "r"(a[0]), "r"(a[1]), "r"(a[2]), "r"(a[3]), "r"(b0), "r"(b1));
}
__device__ __forceinline__ uint32_t pack_h2(float a, float b) {
    __half2 v = __floats2half2_rn(a, b);
    return *reinterpret_cast<uint32_t*>(&v);
}

// ---------------------------------------------------------------------
// Convert fp32 -> fp16
// ---------------------------------------------------------------------
__global__ __launch_bounds__(256)
void conv_f16(const float* __restrict__ x, __half* __restrict__ hi, int n)
{
    int i = (blockIdx.x * 256 + threadIdx.x) * 4;
    if (i >= n) return;
    float4 v = *(const float4*)(x + i);
    *(__half2*)(hi + i)     = __floats2half2_rn(v.x, v.y);
    *(__half2*)(hi + i + 2) = __floats2half2_rn(v.z, v.w);
}

// ---------------------------------------------------------------------
// Tensor-core GEMM (single product): C = A[M,K] @ B[N,K]^T + bias[N]
// mode 0: C fp32; mode 1: Ch fp16
// 3-stage cp.async pipeline, 2 CTAs/SM.
// ---------------------------------------------------------------------
#define STAGES 3
#define SSTAGE 20480          // A 10240 + B 10240
#define GEMM_SMEM (STAGES * SSTAGE)   // 61440 -> 2 CTAs/SM

__global__ __launch_bounds__(256, 2)
void gemm_mma(const __half* __restrict__ A, const __half* __restrict__ B,
              const float* __restrict__ bias, float* __restrict__ C,
              __half* __restrict__ Ch, int mode, int N, int K)
{
    extern __shared__ __align__(128) char smem[];
    const uint32_t sbase = smem_u32(smem);

    const int tid  = threadIdx.x;
    const int lane = tid & 31;
    const int wid  = tid >> 5;

    // banded CTA swizzle (L2-friendly)
    const int id    = blockIdx.y * gridDim.x + blockIdx.x;
    const int bandw = 8 * gridDim.x;
    const int band  = id / bandw;
    const int rem   = id - band * bandw;
    const int bm = (band * 8 + (rem & 7)) * 128;
    const int bn = (rem >> 3) * 128;

    const int wm = (wid >> 2) * 64;
    const int wn = (wid & 3) * 32;

    const uint32_t aoff = (uint32_t)((wm + (lane & 15)) * 80 + (lane >> 4) * 16);
    const uint32_t boff = (uint32_t)(10240 + (wn + (lane & 15)) * 80 + (lane >> 4) * 16);

    const __half* Abase = A + (size_t)bm * K;
    const __half* Bbase = B + (size_t)bn * K;

    float c[4][4][4];
    #pragma unroll
    for (int i = 0; i < 4; i++)
        #pragma unroll
        for (int j = 0; j < 4; j++)
            #pragma unroll
            for (int q = 0; q < 4; q++) c[i][j][q] = 0.0f;

    const int nk = K >> 5;

    auto issue = [&](int kt, int slot) {
        const int koff = kt * 32;
        const uint32_t st = sbase + slot * SSTAGE;
        #pragma unroll
        for (int it = 0; it < 2; it++) {
            int idx = tid + it * 256;
            int row = idx >> 2;
            int c16 = idx & 3;
            cp_async16(st + row * 80 + c16 * 16,
                       Abase + (size_t)row * K + koff + c16 * 8);
            cp_async16(st + 10240 + row * 80 + c16 * 16,
                       Bbase + (size_t)row * K + koff + c16 * 8);
        }
    };

    issue(0, 0); cp_commit();
    issue(1, 1); cp_commit();

    for (int kt = 0; kt < nk; kt++) {
        cp_wait<1>();
        __syncthreads();   // stage kt ready; prior reads of recycled slot done

        const int nxt = kt + 2;
        if (nxt < nk) { issue(nxt, nxt % STAGES); }
        cp_commit();

        const uint32_t st = sbase + (kt % STAGES) * SSTAGE;
        #pragma unroll
        for (int kk = 0; kk < 2; kk++) {
            uint32_t ah[4][4], bh[2][4];
            #pragma unroll
            for (int i = 0; i < 4; i++)
                ldsm4(ah[i], st + aoff + i * 1280 + kk * 32);
            #pragma unroll
            for (int j2 = 0; j2 < 2; j2++)
                ldsm4(bh[j2], st + boff + j2 * 1280 + kk * 32);
            #pragma unroll
            for (int i = 0; i < 4; i++)
                #pragma unroll
                for (int j = 0; j < 4; j++) {
                    const int j2 = j >> 1, sl = j & 1;
                    mma16816(c[i][j], ah[i], bh[j2][sl], bh[j2][sl + 2]);
                }
        }
    }

    const int g = lane >> 2, t = lane & 3;
    #pragma unroll
    for (int j = 0; j < 4; j++) {
        const int col = bn + wn + j * 8 + t * 2;
        const float b0 = bias[col], b1 = bias[col + 1];
        #pragma unroll
        for (int i = 0; i < 4; i++) {
            const int row0 = bm + wm + i * 16 + g;
            float x0 = c[i][j][0] + b0, x1 = c[i][j][1] + b1;
            float x2 = c[i][j][2] + b0, x3 = c[i][j][3] + b1;
            if (mode == 0) {
                *(float2*)(C + (size_t)row0 * N + col)       = make_float2(x0, x1);
                *(float2*)(C + (size_t)(row0 + 8) * N + col) = make_float2(x2, x3);
            } else {
                *(__half2*)(Ch + (size_t)row0 * N + col)       = __floats2half2_rn(x0, x1);
                *(__half2*)(Ch + (size_t)(row0 + 8) * N + col) = __floats2half2_rn(x2, x3);
            }
        }
    }
}

// =====================================================================
// Tensorized flash attention (causal): Br=128, Bc=64, 8 warps
// QK: Q(11b) x K(11b) — 1 product. PV: Ph/Pl (22b) x V(11b) — 2 products.
// =====================================================================
#define ASTR 272
#define QTILE (128 * ASTR)             // 34816
#define KVTILE (64 * ASTR)             // 17408
#define KVSTAGE (2 * KVTILE)           // Kh + Vh = 34816
#define FLASH_SMEM (QTILE + 2 * KVSTAGE)   // 104448 -> try 2 CTAs/SM

__global__ __launch_bounds__(256, 2)
void flash_attn_mma(const __half* __restrict__ qkvh, __half* __restrict__ ctxh)
{
    extern __shared__ __align__(128) char smem[];
    const uint32_t sb = smem_u32(smem);

    const int tid  = threadIdx.x;
    const int lane = tid & 31;
    const int wid  = tid >> 5;
    const int h  = blockIdx.y;
    const int qb = gridDim.x - 1 - blockIdx.x;
    const int q0w = qb * 128 + wid * 16;
    const int nkb = 2 * qb + 2;
    const float scale = 0.08838834764831845f;

    {
        const size_t qrow = (size_t)(qb * 128) * QKVC + h * HD;
        const __half* qsrc = qkvh + qrow;
        #pragma unroll
        for (int it = 0; it < 8; it++) {
            int idx = tid + it * 256;
            int row = idx >> 4, ch = idx & 15;
            cp_async16(sb + row * ASTR + ch * 16,
                       qsrc + (size_t)row * QKVC + ch * 8);
        }
    }

    auto issueKV = [&](int kb, int slot) {
        const size_t roff = (size_t)(kb * 64) * QKVC + h * HD;
        const __half* base[2] = { qkvh + EM + roff, qkvh + 2 * EM + roff };
        const uint32_t st = sb + QTILE + slot * KVSTAGE;
        #pragma unroll
        for (int it = 0; it < 8; it++) {
            int idx = tid + it * 256;
            int arr = idx >> 10, rem = idx & 1023;
            int row = rem >> 4, ch = rem & 15;
            cp_async16(st + arr * KVTILE + row * ASTR + ch * 16,
                       base[arr] + (size_t)row * QKVC + ch * 8);
        }
    };

    issueKV(0, 0); cp_commit();
    issueKV(1, 1); cp_commit();

    float m[2] = { -1e30f, -1e30f };
    float l[2] = { 0.0f, 0.0f };
    float o[16][4];
    #pragma unroll
    for (int n = 0; n < 16; n++)
        #pragma unroll
        for (int q = 0; q < 4; q++) o[n][q] = 0.0f;

    const int g = lane >> 2, t = lane & 3;
    const uint32_t qaddr = sb + (wid * 16 + (lane & 15)) * ASTR + (lane >> 4) * 16;
    const uint32_t kvlane = (uint32_t)((lane & 15) * ASTR + (lane >> 4) * 16);

    for (int kb = 0; kb < nkb; kb++) {
        cp_wait<1>();
        __syncthreads();

        const int slot = kb & 1;
        const uint32_t kB = sb + QTILE + slot * KVSTAGE;
        const uint32_t vB = kB + KVTILE;
        const bool skip = (kb * 64 > q0w + 15);

        if (!skip) {
            float s[8][4];
            #pragma unroll
            for (int j = 0; j < 8; j++)
                #pragma unroll
                for (int q = 0; q < 4; q++) s[j][q] = 0.0f;

            #pragma unroll
            for (int ks = 0; ks < 8; ks++) {
                uint32_t ah4[4];
                ldsm4(ah4, qaddr + ks * 32);
                #pragma unroll
                for (int p2 = 0; p2 < 4; p2++) {
                    uint32_t bh4[4];
                    ldsm4(bh4, kB + kvlane + p2 * (16 * ASTR) + ks * 32);
                    #pragma unroll
                    for (int sl = 0; sl < 2; sl++)
                        mma16816(s[p2 * 2 + sl], ah4, bh4[sl], bh4[sl + 2]);
                }
            }

            const bool dm = (kb * 64 + 63 > q0w);
            const int r0 = q0w + g, r1 = q0w + 8 + g;
            float mx0 = -1e30f, mx1 = -1e30f;
            #pragma unroll
            for (int j = 0; j < 8; j++) {
                const int col = kb * 64 + 8 * j + 2 * t;
                float v0 = s[j][0] * scale, v1 = s[j][1] * scale;
                float v2 = s[j][2] * scale, v3 = s[j][3] * scale;
                if (dm) {
                    if (col     > r0) v0 = -1e30f;
                    if (col + 1 > r0) v1 = -1e30f;
                    if (col     > r1) v2 = -1e30f;
                    if (col + 1 > r1) v3 = -1e30f;
                }
                s[j][0] = v0; s[j][1] = v1; s[j][2] = v2; s[j][3] = v3;
                mx0 = fmaxf(mx0, fmaxf(v0, v1));
                mx1 = fmaxf(mx1, fmaxf(v2, v3));
            }
            mx0 = fmaxf(mx0, __shfl_xor_sync(0xffffffffu, mx0, 1));
            mx0 = fmaxf(mx0, __shfl_xor_sync(0xffffffffu, mx0, 2));
            mx1 = fmaxf(mx1, __shfl_xor_sync(0xffffffffu, mx1, 1));
            mx1 = fmaxf(mx1, __shfl_xor_sync(0xffffffffu, mx1, 2));

            const float mn0 = fmaxf(m[0], mx0);
            const float mn1 = fmaxf(m[1], mx1);
            float rs0 = 0.0f, rs1 = 0.0f;
            #pragma unroll
            for (int j = 0; j < 8; j++) {
                s[j][0] = __expf(s[j][0] - mn0);
                s[j][1] = __expf(s[j][1] - mn0);
                s[j][2] = __expf(s[j][2] - mn1);
                s[j][3] = __expf(s[j][3] - mn1);
                rs0 += s[j][0] + s[j][1];
                rs1 += s[j][2] + s[j][3];
            }
            rs0 += __shfl_xor_sync(0xffffffffu, rs0, 1);
            rs0 += __shfl_xor_sync(0xffffffffu, rs0, 2);
            rs1 += __shfl_xor_sync(0xffffffffu, rs1, 1);
            rs1 += __shfl_xor_sync(0xffffffffu, rs1, 2);

            const float f0 = __expf(m[0] - mn0);
            const float f1 = __expf(m[1] - mn1);
            l[0] = l[0] * f0 + rs0; l[1] = l[1] * f1 + rs1;
            m[0] = mn0; m[1] = mn1;
            #pragma unroll
            for (int n = 0; n < 16; n++) {
                o[n][0] *= f0; o[n][1] *= f0;
                o[n][2] *= f1; o[n][3] *= f1;
            }

            #pragma unroll
            for (int jp = 0; jp < 4; jp++) {
                uint32_t ph[4], pl[4];
                {
                    const float* p0 = s[2 * jp];
                    const float* p1 = s[2 * jp + 1];
                    ph[0] = pack_h2(p0[0], p0[1]);
                    ph[1] = pack_h2(p0[2], p0[3]);
                    ph[2] = pack_h2(p1[0], p1[1]);
                    ph[3] = pack_h2(p1[2], p1[3]);
                    __half2* hp;
                    hp = (__half2*)&ph[0];
                    pl[0] = pack_h2(p0[0] - __half2float(hp->x), p0[1] - __half2float(hp->y));
                    hp = (__half2*)&ph[1];
                    pl[1] = pack_h2(p0[2] - __half2float(hp->x), p0[3] - __half2float(hp->y));
                    hp = (__half2*)&ph[2];
                    pl[2] = pack_h2(p1[0] - __half2float(hp->x), p1[1] - __half2float(hp->y));
                    hp = (__half2*)&ph[3];
                    pl[3] = pack_h2(p1[2] - __half2float(hp->x), p1[3] - __half2float(hp->y));
                }
                #pragma unroll
                for (int np = 0; np < 8; np++) {
                    uint32_t bh4[4];
                    ldsm4t(bh4, vB + kvlane + jp * (16 * ASTR) + np * 32);
                    mma16816(o[2 * np],     ph, bh4[0], bh4[1]);
                    mma16816(o[2 * np],     pl, bh4[0], bh4[1]);
                    mma16816(o[2 * np + 1], ph, bh4[2], bh4[3]);
                    mma16816(o[2 * np + 1], pl, bh4[2], bh4[3]);
                }
            }
        }

        __syncthreads();
        if (kb + 2 < nkb) issueKV(kb + 2, slot);
        cp_commit();
    }

    const float inv0 = 1.0f / l[0];
    const float inv1 = 1.0f / l[1];
    const int r0 = q0w + g, r1 = q0w + 8 + g;
    #pragma unroll
    for (int n = 0; n < 16; n++) {
        const int col = h * HD + n * 8 + 2 * t;
        *(__half2*)(ctxh + (size_t)r0 * EM + col) =
            __floats2half2_rn(o[n][0] * inv0, o[n][1] * inv0);
        *(__half2*)(ctxh + (size_t)r1 * EM + col) =
            __floats2half2_rn(o[n][2] * inv1, o[n][3] * inv1);
    }
}

// =====================================================================
extern "C" void kernel_launch(void* const* d_in, const int* in_sizes, int n_in,
                              void* d_out, int out_size)
{
    (void)in_sizes; (void)n_in; (void)out_size;
    const float* hs   = (const float*)d_in[0];
    const float* wqkv = (const float*)d_in[1];
    const float* bqkv = (const float*)d_in[2];
    const float* wo   = (const float*)d_in[3];
    const float* bo   = (const float*)d_in[4];
    float* out = (float*)d_out;

    __half *qkvh, *ah, *bh;
    cudaGetSymbolAddress((void**)&qkvh, g_qkvh);
    cudaGetSymbolAddress((void**)&ah, g_ah);
    cudaGetSymbolAddress((void**)&bh, g_bh);

    cudaFuncSetAttribute(gemm_mma, cudaFuncAttributeMaxDynamicSharedMemorySize, GEMM_SMEM);
    cudaFuncSetAttribute(flash_attn_mma, cudaFuncAttributeMaxDynamicSharedMemorySize, FLASH_SMEM);

    // 1) convert inputs to fp16
    conv_f16<<<(SQ * EM / 4 + 255) / 256, 256>>>(hs, ah, SQ * EM);
    conv_f16<<<(QKVC * EM / 4 + 255) / 256, 256>>>(wqkv, bh, QKVC * EM);

    // 2) QKV projection -> fp16
    dim3 g1(QKVC / 128, SQ / 128);
    gemm_mma<<<g1, 256, GEMM_SMEM>>>(ah, bh, bqkv, nullptr, qkvh, 1, QKVC, EM);

    // 3) convert Wo (stream-ordered after gemm1's reads of bh)
    conv_f16<<<(EM * EM / 4 + 255) / 256, 256>>>(wo, bh, EM * EM);

    // 4) causal flash attention -> ctx fp16 (overwrites ah)
    dim3 g2(SQ / 128, NH);
    flash_attn_mma<<<g2, 256, FLASH_SMEM>>>(qkvh, ah);

    // 5) output projection -> fp32 out
    dim3 g3(EM / 128, SQ / 128);
    gemm_mma<<<g3, 256, GEMM_SMEM>>>(ah, bh, bo, out, nullptr, 0, EM, EM);
}

// round 9
// speedup vs baseline: 6.3959x; 1.1261x over previous
#include <cuda_runtime.h>
#include <cuda_fp16.h>
#include <math.h>
#include <cstdint>

#define SQ   4096
#define EM   2048
#define NH   16
#define HD   128
#define QKVC (3*EM)

// ---------------------------------------------------------------------
// Scratch (allocation-free rule: device globals)
// ---------------------------------------------------------------------
__device__ __half g_qkvh[(size_t)SQ * QKVC];   // qkv (fp16)
__device__ __half g_ah[(size_t)SQ * EM];       // A (hs, then ctx) fp16
__device__ __half g_bh[(size_t)QKVC * EM];     // W (Wqkv, then Wo) fp16

// ---------------------------------------------------------------------
// Portable PTX helpers
// ---------------------------------------------------------------------
__device__ __forceinline__ uint32_t smem_u32(const void* p) {
    uint32_t a;
    asm("{ .reg .u64 t; cvta.to.shared.u64 t, %1; cvt.u32.u64 %0, t; }" : "=r"(a) : "l"(p));
    return a;
}
__device__ __forceinline__ void cp_async16(uint32_t saddr, const void* gaddr) {
    asm volatile("cp.async.cg.shared.global [%0], [%1], 16;" :: "r"(saddr), "l"(gaddr));
}
__device__ __forceinline__ void cp_commit() { asm volatile("cp.async.commit_group;"); }
template <int N>
__device__ __forceinline__ void cp_wait() { asm volatile("cp.async.wait_group %0;" :: "n"(N)); }

__device__ __forceinline__ void ldsm4(uint32_t* r, uint32_t addr) {
    asm volatile("ldmatrix.sync.aligned.m8n8.x4.shared.b16 {%0,%1,%2,%3}, [%4];"
        : "=r"(r[0]), "=r"(r[1]), "=r"(r[2]), "=r"(r[3]) : "r"(addr));
}
__device__ __forceinline__ void ldsm4t(uint32_t* r, uint32_t addr) {
    asm volatile("ldmatrix.sync.aligned.m8n8.x4.trans.shared.b16 {%0,%1,%2,%3}, [%4];"
        : "=r"(r[0]), "=r"(r[1]), "=r"(r[2]), "=r"(r[3]) : "r"(addr));
}
__device__ __forceinline__ void mma16816(float* c, const uint32_t* a, uint32_t b0, uint32_t b1) {
    asm volatile("mma.sync.aligned.m16n8k16.row.col.f32.f16.f16.f32 "
        "{%0,%1,%2,%3}, {%4,%5,%6,%7}, {%8,%9}, {%0,%1,%2,%3};"
        : "+f"(c[0]), "+f"(c[1]), "+f"(c[2]), "+f"(c[3])
        : "r"(a[0]), "r"(a[1]), "r"(a[2]), "r"(a[3]), "r"(b0), "r"(b1));
}
__device__ __forceinline__ uint32_t pack_h2(float a, float b) {
    __half2 v = __floats2half2_rn(a, b);
    return *reinterpret_cast<uint32_t*>(&v);
}

// ---------------------------------------------------------------------
// Convert fp32 -> fp16 — 16 elems/thread (4 independent float4: MLP=4)
// ---------------------------------------------------------------------
__global__ __launch_bounds__(256)
void conv_f16(const float* __restrict__ x, __half* __restrict__ hi, int n)
{
    int base = (blockIdx.x * 256 + threadIdx.x) * 16;
    if (base >= n) return;
    float4 v0 = *(const float4*)(x + base);
    float4 v1 = *(const float4*)(x + base + 4);
    float4 v2 = *(const float4*)(x + base + 8);
    float4 v3 = *(const float4*)(x + base + 12);
    __half2 h[8];
    h[0] = __floats2half2_rn(v0.x, v0.y); h[1] = __floats2half2_rn(v0.z, v0.w);
    h[2] = __floats2half2_rn(v1.x, v1.y); h[3] = __floats2half2_rn(v1.z, v1.w);
    h[4] = __floats2half2_rn(v2.x, v2.y); h[5] = __floats2half2_rn(v2.z, v2.w);
    h[6] = __floats2half2_rn(v3.x, v3.y); h[7] = __floats2half2_rn(v3.z, v3.w);
    *(uint4*)(hi + base)     = *(uint4*)&h[0];
    *(uint4*)(hi + base + 8) = *(uint4*)&h[4];
}

// ---------------------------------------------------------------------
// Tensor-core GEMM (single product): C = A[M,K] @ B[N,K]^T + bias[N]
// mode 0: C fp32; mode 1: Ch fp16
// 3-stage cp.async pipeline, 2 CTAs/SM.
// ---------------------------------------------------------------------
#define STAGES 3
#define SSTAGE 20480          // A 10240 + B 10240
#define GEMM_SMEM (STAGES * SSTAGE)   // 61440 -> 2 CTAs/SM

__global__ __launch_bounds__(256, 2)
void gemm_mma(const __half* __restrict__ A, const __half* __restrict__ B,
              const float* __restrict__ bias, float* __restrict__ C,
              __half* __restrict__ Ch, int mode, int N, int K)
{
    extern __shared__ __align__(128) char smem[];
    const uint32_t sbase = smem_u32(smem);

    const int tid  = threadIdx.x;
    const int lane = tid & 31;
    const int wid  = tid >> 5;

    // banded CTA swizzle (L2-friendly)
    const int id    = blockIdx.y * gridDim.x + blockIdx.x;
    const int bandw = 8 * gridDim.x;
    const int band  = id / bandw;
    const int rem   = id - band * bandw;
    const int bm = (band * 8 + (rem & 7)) * 128;
    const int bn = (rem >> 3) * 128;

    const int wm = (wid >> 2) * 64;
    const int wn = (wid & 3) * 32;

    const uint32_t aoff = (uint32_t)((wm + (lane & 15)) * 80 + (lane >> 4) * 16);
    const uint32_t boff = (uint32_t)(10240 + (wn + (lane & 15)) * 80 + (lane >> 4) * 16);

    const __half* Abase = A + (size_t)bm * K;
    const __half* Bbase = B + (size_t)bn * K;

    float c[4][4][4];
    #pragma unroll
    for (int i = 0; i < 4; i++)
        #pragma unroll
        for (int j = 0; j < 4; j++)
            #pragma unroll
            for (int q = 0; q < 4; q++) c[i][j][q] = 0.0f;

    const int nk = K >> 5;

    auto issue = [&](int kt, int slot) {
        const int koff = kt * 32;
        const uint32_t st = sbase + slot * SSTAGE;
        #pragma unroll
        for (int it = 0; it < 2; it++) {
            int idx = tid + it * 256;
            int row = idx >> 2;
            int c16 = idx & 3;
            cp_async16(st + row * 80 + c16 * 16,
                       Abase + (size_t)row * K + koff + c16 * 8);
            cp_async16(st + 10240 + row * 80 + c16 * 16,
                       Bbase + (size_t)row * K + koff + c16 * 8);
        }
    };

    issue(0, 0); cp_commit();
    issue(1, 1); cp_commit();

    for (int kt = 0; kt < nk; kt++) {
        cp_wait<1>();
        __syncthreads();

        const int nxt = kt + 2;
        if (nxt < nk) { issue(nxt, nxt % STAGES); }
        cp_commit();

        const uint32_t st = sbase + (kt % STAGES) * SSTAGE;
        #pragma unroll
        for (int kk = 0; kk < 2; kk++) {
            uint32_t ah[4][4], bh[2][4];
            #pragma unroll
            for (int i = 0; i < 4; i++)
                ldsm4(ah[i], st + aoff + i * 1280 + kk * 32);
            #pragma unroll
            for (int j2 = 0; j2 < 2; j2++)
                ldsm4(bh[j2], st + boff + j2 * 1280 + kk * 32);
            #pragma unroll
            for (int i = 0; i < 4; i++)
                #pragma unroll
                for (int j = 0; j < 4; j++) {
                    const int j2 = j >> 1, sl = j & 1;
                    mma16816(c[i][j], ah[i], bh[j2][sl], bh[j2][sl + 2]);
                }
        }
    }

    const int g = lane >> 2, t = lane & 3;
    #pragma unroll
    for (int j = 0; j < 4; j++) {
        const int col = bn + wn + j * 8 + t * 2;
        const float b0 = bias[col], b1 = bias[col + 1];
        #pragma unroll
        for (int i = 0; i < 4; i++) {
            const int row0 = bm + wm + i * 16 + g;
            float x0 = c[i][j][0] + b0, x1 = c[i][j][1] + b1;
            float x2 = c[i][j][2] + b0, x3 = c[i][j][3] + b1;
            if (mode == 0) {
                *(float2*)(C + (size_t)row0 * N + col)       = make_float2(x0, x1);
                *(float2*)(C + (size_t)(row0 + 8) * N + col) = make_float2(x2, x3);
            } else {
                *(__half2*)(Ch + (size_t)row0 * N + col)       = __floats2half2_rn(x0, x1);
                *(__half2*)(Ch + (size_t)(row0 + 8) * N + col) = __floats2half2_rn(x2, x3);
            }
        }
    }
}

// =====================================================================
// Tensorized flash attention (causal): Br=128, Bc=64, 8 warps
// QK: 1 product. PV: 1 product (P hi only).
// =====================================================================
#define ASTR 272
#define QTILE (128 * ASTR)             // 34816
#define KVTILE (64 * ASTR)             // 17408
#define KVSTAGE (2 * KVTILE)           // K + V = 34816
#define FLASH_SMEM (QTILE + 2 * KVSTAGE)   // 104448 -> 2 CTAs/SM

__global__ __launch_bounds__(256, 2)
void flash_attn_mma(const __half* __restrict__ qkvh, __half* __restrict__ ctxh)
{
    extern __shared__ __align__(128) char smem[];
    const uint32_t sb = smem_u32(smem);

    const int tid  = threadIdx.x;
    const int lane = tid & 31;
    const int wid  = tid >> 5;
    const int h  = blockIdx.y;
    const int qb = gridDim.x - 1 - blockIdx.x;
    const int q0w = qb * 128 + wid * 16;
    const int nkb = 2 * qb + 2;
    const float scale = 0.08838834764831845f;

    {
        const size_t qrow = (size_t)(qb * 128) * QKVC + h * HD;
        const __half* qsrc = qkvh + qrow;
        #pragma unroll
        for (int it = 0; it < 8; it++) {
            int idx = tid + it * 256;
            int row = idx >> 4, ch = idx & 15;
            cp_async16(sb + row * ASTR + ch * 16,
                       qsrc + (size_t)row * QKVC + ch * 8);
        }
    }

    auto issueKV = [&](int kb, int slot) {
        const size_t roff = (size_t)(kb * 64) * QKVC + h * HD;
        const __half* base[2] = { qkvh + EM + roff, qkvh + 2 * EM + roff };
        const uint32_t st = sb + QTILE + slot * KVSTAGE;
        #pragma unroll
        for (int it = 0; it < 8; it++) {
            int idx = tid + it * 256;
            int arr = idx >> 10, rem = idx & 1023;
            int row = rem >> 4, ch = rem & 15;
            cp_async16(st + arr * KVTILE + row * ASTR + ch * 16,
                       base[arr] + (size_t)row * QKVC + ch * 8);
        }
    };

    issueKV(0, 0); cp_commit();
    issueKV(1, 1); cp_commit();

    float m[2] = { -1e30f, -1e30f };
    float l[2] = { 0.0f, 0.0f };
    float o[16][4];
    #pragma unroll
    for (int n = 0; n < 16; n++)
        #pragma unroll
        for (int q = 0; q < 4; q++) o[n][q] = 0.0f;

    const int g = lane >> 2, t = lane & 3;
    const uint32_t qaddr = sb + (wid * 16 + (lane & 15)) * ASTR + (lane >> 4) * 16;
    const uint32_t kvlane = (uint32_t)((lane & 15) * ASTR + (lane >> 4) * 16);

    for (int kb = 0; kb < nkb; kb++) {
        cp_wait<1>();
        __syncthreads();

        const int slot = kb & 1;
        const uint32_t kB = sb + QTILE + slot * KVSTAGE;
        const uint32_t vB = kB + KVTILE;
        const bool skip = (kb * 64 > q0w + 15);

        if (!skip) {
            float s[8][4];
            #pragma unroll
            for (int j = 0; j < 8; j++)
                #pragma unroll
                for (int q = 0; q < 4; q++) s[j][q] = 0.0f;

            #pragma unroll
            for (int ks = 0; ks < 8; ks++) {
                uint32_t ah4[4];
                ldsm4(ah4, qaddr + ks * 32);
                #pragma unroll
                for (int p2 = 0; p2 < 4; p2++) {
                    uint32_t bh4[4];
                    ldsm4(bh4, kB + kvlane + p2 * (16 * ASTR) + ks * 32);
                    #pragma unroll
                    for (int sl = 0; sl < 2; sl++)
                        mma16816(s[p2 * 2 + sl], ah4, bh4[sl], bh4[sl + 2]);
                }
            }

            const bool dm = (kb * 64 + 63 > q0w);
            const int r0 = q0w + g, r1 = q0w + 8 + g;
            float mx0 = -1e30f, mx1 = -1e30f;
            #pragma unroll
            for (int j = 0; j < 8; j++) {
                const int col = kb * 64 + 8 * j + 2 * t;
                float v0 = s[j][0] * scale, v1 = s[j][1] * scale;
                float v2 = s[j][2] * scale, v3 = s[j][3] * scale;
                if (dm) {
                    if (col     > r0) v0 = -1e30f;
                    if (col + 1 > r0) v1 = -1e30f;
                    if (col     > r1) v2 = -1e30f;
                    if (col + 1 > r1) v3 = -1e30f;
                }
                s[j][0] = v0; s[j][1] = v1; s[j][2] = v2; s[j][3] = v3;
                mx0 = fmaxf(mx0, fmaxf(v0, v1));
                mx1 = fmaxf(mx1, fmaxf(v2, v3));
            }
            mx0 = fmaxf(mx0, __shfl_xor_sync(0xffffffffu, mx0, 1));
            mx0 = fmaxf(mx0, __shfl_xor_sync(0xffffffffu, mx0, 2));
            mx1 = fmaxf(mx1, __shfl_xor_sync(0xffffffffu, mx1, 1));
            mx1 = fmaxf(mx1, __shfl_xor_sync(0xffffffffu, mx1, 2));

            const float mn0 = fmaxf(m[0], mx0);
            const float mn1 = fmaxf(m[1], mx1);
            float rs0 = 0.0f, rs1 = 0.0f;
            #pragma unroll
            for (int j = 0; j < 8; j++) {
                s[j][0] = __expf(s[j][0] - mn0);
                s[j][1] = __expf(s[j][1] - mn0);
                s[j][2] = __expf(s[j][2] - mn1);
                s[j][3] = __expf(s[j][3] - mn1);
                rs0 += s[j][0] + s[j][1];
                rs1 += s[j][2] + s[j][3];
            }
            rs0 += __shfl_xor_sync(0xffffffffu, rs0, 1);
            rs0 += __shfl_xor_sync(0xffffffffu, rs0, 2);
            rs1 += __shfl_xor_sync(0xffffffffu, rs1, 1);
            rs1 += __shfl_xor_sync(0xffffffffu, rs1, 2);

            const float f0 = __expf(m[0] - mn0);
            const float f1 = __expf(m[1] - mn1);
            l[0] = l[0] * f0 + rs0; l[1] = l[1] * f1 + rs1;
            m[0] = mn0; m[1] = mn1;
            #pragma unroll
            for (int n = 0; n < 16; n++) {
                o[n][0] *= f0; o[n][1] *= f0;
                o[n][2] *= f1; o[n][3] *= f1;
            }

            #pragma unroll
            for (int jp = 0; jp < 4; jp++) {
                uint32_t ph[4];
                {
                    const float* p0 = s[2 * jp];
                    const float* p1 = s[2 * jp + 1];
                    ph[0] = pack_h2(p0[0], p0[1]);
                    ph[1] = pack_h2(p0[2], p0[3]);
                    ph[2] = pack_h2(p1[0], p1[1]);
                    ph[3] = pack_h2(p1[2], p1[3]);
                }
                #pragma unroll
                for (int np = 0; np < 8; np++) {
                    uint32_t bh4[4];
                    ldsm4t(bh4, vB + kvlane + jp * (16 * ASTR) + np * 32);
                    mma16816(o[2 * np],     ph, bh4[0], bh4[1]);
                    mma16816(o[2 * np + 1], ph, bh4[2], bh4[3]);
                }
            }
        }

        __syncthreads();
        if (kb + 2 < nkb) issueKV(kb + 2, slot);
        cp_commit();
    }

    const float inv0 = 1.0f / l[0];
    const float inv1 = 1.0f / l[1];
    const int r0 = q0w + g, r1 = q0w + 8 + g;
    #pragma unroll
    for (int n = 0; n < 16; n++) {
        const int col = h * HD + n * 8 + 2 * t;
        *(__half2*)(ctxh + (size_t)r0 * EM + col) =
            __floats2half2_rn(o[n][0] * inv0, o[n][1] * inv0);
        *(__half2*)(ctxh + (size_t)r1 * EM + col) =
            __floats2half2_rn(o[n][2] * inv1, o[n][3] * inv1);
    }
}

// =====================================================================
extern "C" void kernel_launch(void* const* d_in, const int* in_sizes, int n_in,
                              void* d_out, int out_size)
{
    (void)in_sizes; (void)n_in; (void)out_size;
    const float* hs   = (const float*)d_in[0];
    const float* wqkv = (const float*)d_in[1];
    const float* bqkv = (const float*)d_in[2];
    const float* wo   = (const float*)d_in[3];
    const float* bo   = (const float*)d_in[4];
    float* out = (float*)d_out;

    __half *qkvh, *ah, *bh;
    cudaGetSymbolAddress((void**)&qkvh, g_qkvh);
    cudaGetSymbolAddress((void**)&ah, g_ah);
    cudaGetSymbolAddress((void**)&bh, g_bh);

    cudaFuncSetAttribute(gemm_mma, cudaFuncAttributeMaxDynamicSharedMemorySize, GEMM_SMEM);
    cudaFuncSetAttribute(flash_attn_mma, cudaFuncAttributeMaxDynamicSharedMemorySize, FLASH_SMEM);

    // 1) convert inputs to fp16 (16 elems/thread)
    conv_f16<<<(SQ * EM / 16 + 255) / 256, 256>>>(hs, ah, SQ * EM);
    conv_f16<<<(QKVC * EM / 16 + 255) / 256, 256>>>(wqkv, bh, QKVC * EM);

    // 2) QKV projection -> fp16
    dim3 g1(QKVC / 128, SQ / 128);
    gemm_mma<<<g1, 256, GEMM_SMEM>>>(ah, bh, bqkv, nullptr, qkvh, 1, QKVC, EM);

    // 3) convert Wo (stream-ordered after gemm1's reads of bh)
    conv_f16<<<(EM * EM / 16 + 255) / 256, 256>>>(wo, bh, EM * EM);

    // 4) causal flash attention -> ctx fp16 (overwrites ah)
    dim3 g2(SQ / 128, NH);
    flash_attn_mma<<<g2, 256, FLASH_SMEM>>>(qkvh, ah);

    // 5) output projection -> fp32 out
    dim3 g3(EM / 128, SQ / 128);
    gemm_mma<<<g3, 256, GEMM_SMEM>>>(ah, bh, bo, out, nullptr, 0, EM, EM);
}

// round 10
// speedup vs baseline: 7.7169x; 1.2065x over previous
#include <cuda_runtime.h>
#include <cuda_fp16.h>
#include <math.h>
#include <cstdint>

#define SQ   4096
#define EM   2048
#define NH   16
#define HD   128
#define QKVC (3*EM)

// ---------------------------------------------------------------------
// Scratch (allocation-free rule: device globals)
// ---------------------------------------------------------------------
__device__ __half g_qkvh[(size_t)SQ * QKVC];   // qkv (fp16)
__device__ __half g_ah[(size_t)SQ * EM];       // A (hs, then ctx) fp16
__device__ __half g_bh[(size_t)QKVC * EM];     // W (Wqkv, then Wo) fp16

// ---------------------------------------------------------------------
// Portable PTX helpers
// ---------------------------------------------------------------------
__device__ __forceinline__ uint32_t smem_u32(const void* p) {
    uint32_t a;
    asm("{ .reg .u64 t; cvta.to.shared.u64 t, %1; cvt.u32.u64 %0, t; }" : "=r"(a) : "l"(p));
    return a;
}
__device__ __forceinline__ void cp_async16(uint32_t saddr, const void* gaddr) {
    asm volatile("cp.async.cg.shared.global [%0], [%1], 16;" :: "r"(saddr), "l"(gaddr));
}
__device__ __forceinline__ void cp_commit() { asm volatile("cp.async.commit_group;"); }
template <int N>
__device__ __forceinline__ void cp_wait() { asm volatile("cp.async.wait_group %0;" :: "n"(N)); }

__device__ __forceinline__ void ldsm4(uint32_t* r, uint32_t addr) {
    asm volatile("ldmatrix.sync.aligned.m8n8.x4.shared.b16 {%0,%1,%2,%3}, [%4];"
        : "=r"(r[0]), "=r"(r[1]), "=r"(r[2]), "=r"(r[3]) : "r"(addr));
}
__device__ __forceinline__ void ldsm4t(uint32_t* r, uint32_t addr) {
    asm volatile("ldmatrix.sync.aligned.m8n8.x4.trans.shared.b16 {%0,%1,%2,%3}, [%4];"
        : "=r"(r[0]), "=r"(r[1]), "=r"(r[2]), "=r"(r[3]) : "r"(addr));
}
__device__ __forceinline__ void mma16816(float* c, const uint32_t* a, uint32_t b0, uint32_t b1) {
    asm volatile("mma.sync.aligned.m16n8k16.row.col.f32.f16.f16.f32 "
        "{%0,%1,%2,%3}, {%4,%5,%6,%7}, {%8,%9}, {%0,%1,%2,%3};"
        : "+f"(c[0]), "+f"(c[1]), "+f"(c[2]), "+f"(c[3])
        : "r"(a[0]), "r"(a[1]), "r"(a[2]), "r"(a[3]), "r"(b0), "r"(b1));
}
__device__ __forceinline__ uint32_t pack_h2(float a, float b) {
    __half2 v = __floats2half2_rn(a, b);
    return *reinterpret_cast<uint32_t*>(&v);
}

// ---------------------------------------------------------------------
// Convert fp32 -> fp16 — 16 elems/thread
// ---------------------------------------------------------------------
__global__ __launch_bounds__(256)
void conv_f16(const float* __restrict__ x, __half* __restrict__ hi, int n)
{
    int base = (blockIdx.x * 256 + threadIdx.x) * 16;
    if (base >= n) return;
    float4 v0 = *(const float4*)(x + base);
    float4 v1 = *(const float4*)(x + base + 4);
    float4 v2 = *(const float4*)(x + base + 8);
    float4 v3 = *(const float4*)(x + base + 12);
    __half2 h[8];
    h[0] = __floats2half2_rn(v0.x, v0.y); h[1] = __floats2half2_rn(v0.z, v0.w);
    h[2] = __floats2half2_rn(v1.x, v1.y); h[3] = __floats2half2_rn(v1.z, v1.w);
    h[4] = __floats2half2_rn(v2.x, v2.y); h[5] = __floats2half2_rn(v2.z, v2.w);
    h[6] = __floats2half2_rn(v3.x, v3.y); h[7] = __floats2half2_rn(v3.z, v3.w);
    *(uint4*)(hi + base)     = *(uint4*)&h[0];
    *(uint4*)(hi + base + 8) = *(uint4*)&h[4];
}

// ---------------------------------------------------------------------
// Tensor-core GEMM: C = A[M,K] @ B[N,K]^T + bias[N]
// 64x128 CTA tile (better wave quantization), 8 warps (2x4) of 32x32,
// 3-stage cp.async, 2 CTAs/SM.
// mode 0: C fp32; mode 1: Ch fp16
// ---------------------------------------------------------------------
#define STAGES 3
#define ATILE 5120            // 64 rows x 80B
#define SSTAGE 15360          // A 5120 + B 10240
#define GEMM_SMEM (STAGES * SSTAGE)   // 46080

__global__ __launch_bounds__(256, 2)
void gemm_mma(const __half* __restrict__ A, const __half* __restrict__ B,
              const float* __restrict__ bias, float* __restrict__ C,
              __half* __restrict__ Ch, int mode, int N, int K)
{
    extern __shared__ __align__(128) char smem[];
    const uint32_t sbase = smem_u32(smem);

    const int tid  = threadIdx.x;
    const int lane = tid & 31;
    const int wid  = tid >> 5;

    // banded CTA swizzle (L2-friendly): 8 bm rows per band
    const int id    = blockIdx.y * gridDim.x + blockIdx.x;
    const int bandw = 8 * gridDim.x;
    const int band  = id / bandw;
    const int rem   = id - band * bandw;
    const int bm = (band * 8 + (rem & 7)) * 64;
    const int bn = (rem >> 3) * 128;

    const int wm = (wid >> 2) * 32;
    const int wn = (wid & 3) * 32;

    const uint32_t aoff = (uint32_t)((wm + (lane & 15)) * 80 + (lane >> 4) * 16);
    const uint32_t boff = (uint32_t)(ATILE + (wn + (lane & 15)) * 80 + (lane >> 4) * 16);

    const __half* Abase = A + (size_t)bm * K;
    const __half* Bbase = B + (size_t)bn * K;

    float c[2][4][4];
    #pragma unroll
    for (int i = 0; i < 2; i++)
        #pragma unroll
        for (int j = 0; j < 4; j++)
            #pragma unroll
            for (int q = 0; q < 4; q++) c[i][j][q] = 0.0f;

    const int nk = K >> 5;

    auto issue = [&](int kt, int slot) {
        const int koff = kt * 32;
        const uint32_t st = sbase + slot * SSTAGE;
        // A: 64 rows x 4 chunks = 256
        {
            int row = tid >> 2, c16 = tid & 3;
            cp_async16(st + row * 80 + c16 * 16,
                       Abase + (size_t)row * K + koff + c16 * 8);
        }
        // B: 128 rows x 4 chunks = 512
        #pragma unroll
        for (int it = 0; it < 2; it++) {
            int idx = tid + it * 256;
            int row = idx >> 2, c16 = idx & 3;
            cp_async16(st + ATILE + row * 80 + c16 * 16,
                       Bbase + (size_t)row * K + koff + c16 * 8);
        }
    };

    issue(0, 0); cp_commit();
    issue(1, 1); cp_commit();

    for (int kt = 0; kt < nk; kt++) {
        cp_wait<1>();
        __syncthreads();

        const int nxt = kt + 2;
        if (nxt < nk) { issue(nxt, nxt % STAGES); }
        cp_commit();

        const uint32_t st = sbase + (kt % STAGES) * SSTAGE;
        #pragma unroll
        for (int kk = 0; kk < 2; kk++) {
            uint32_t ah[2][4], bh[2][4];
            #pragma unroll
            for (int i = 0; i < 2; i++)
                ldsm4(ah[i], st + aoff + i * 1280 + kk * 32);
            #pragma unroll
            for (int j2 = 0; j2 < 2; j2++)
                ldsm4(bh[j2], st + boff + j2 * 1280 + kk * 32);
            #pragma unroll
            for (int i = 0; i < 2; i++)
                #pragma unroll
                for (int j = 0; j < 4; j++) {
                    const int j2 = j >> 1, sl = j & 1;
                    mma16816(c[i][j], ah[i], bh[j2][sl], bh[j2][sl + 2]);
                }
        }
    }

    const int g = lane >> 2, t = lane & 3;
    #pragma unroll
    for (int j = 0; j < 4; j++) {
        const int col = bn + wn + j * 8 + t * 2;
        const float b0 = bias[col], b1 = bias[col + 1];
        #pragma unroll
        for (int i = 0; i < 2; i++) {
            const int row0 = bm + wm + i * 16 + g;
            float x0 = c[i][j][0] + b0, x1 = c[i][j][1] + b1;
            float x2 = c[i][j][2] + b0, x3 = c[i][j][3] + b1;
            if (mode == 0) {
                *(float2*)(C + (size_t)row0 * N + col)       = make_float2(x0, x1);
                *(float2*)(C + (size_t)(row0 + 8) * N + col) = make_float2(x2, x3);
            } else {
                *(__half2*)(Ch + (size_t)row0 * N + col)       = __floats2half2_rn(x0, x1);
                *(__half2*)(Ch + (size_t)(row0 + 8) * N + col) = __floats2half2_rn(x2, x3);
            }
        }
    }
}

// =====================================================================
// Tensorized flash attention (causal): Br=128, Bc=64, 8 warps
// 1-D grid, all-heaviest-first across heads. exp2-based softmax.
// =====================================================================
#define ASTR 272
#define QTILE (128 * ASTR)
#define KVTILE (64 * ASTR)
#define KVSTAGE (2 * KVTILE)
#define FLASH_SMEM (QTILE + 2 * KVSTAGE)   // 104448 -> 2 CTAs/SM

__global__ __launch_bounds__(256, 2)
void flash_attn_mma(const __half* __restrict__ qkvh, __half* __restrict__ ctxh)
{
    extern __shared__ __align__(128) char smem[];
    const uint32_t sb = smem_u32(smem);

    const int tid  = threadIdx.x;
    const int lane = tid & 31;
    const int wid  = tid >> 5;
    // all heavy CTAs (large qb) first, across all heads
    const int h  = blockIdx.x & (NH - 1);
    const int qb = (SQ / 128) - 1 - (blockIdx.x >> 4);
    const int q0w = qb * 128 + wid * 16;
    const int nkb = 2 * qb + 2;
    const float qs = 0.08838834764831845f * 1.4426950408889634f;  // scale*log2(e)

    {
        const size_t qrow = (size_t)(qb * 128) * QKVC + h * HD;
        const __half* qsrc = qkvh + qrow;
        #pragma unroll
        for (int it = 0; it < 8; it++) {
            int idx = tid + it * 256;
            int row = idx >> 4, ch = idx & 15;
            cp_async16(sb + row * ASTR + ch * 16,
                       qsrc + (size_t)row * QKVC + ch * 8);
        }
    }

    auto issueKV = [&](int kb, int slot) {
        const size_t roff = (size_t)(kb * 64) * QKVC + h * HD;
        const __half* base[2] = { qkvh + EM + roff, qkvh + 2 * EM + roff };
        const uint32_t st = sb + QTILE + slot * KVSTAGE;
        #pragma unroll
        for (int it = 0; it < 8; it++) {
            int idx = tid + it * 256;
            int arr = idx >> 10, rem = idx & 1023;
            int row = rem >> 4, ch = rem & 15;
            cp_async16(st + arr * KVTILE + row * ASTR + ch * 16,
                       base[arr] + (size_t)row * QKVC + ch * 8);
        }
    };

    issueKV(0, 0); cp_commit();
    issueKV(1, 1); cp_commit();

    float m[2] = { -1e30f, -1e30f };
    float l[2] = { 0.0f, 0.0f };
    float o[16][4];
    #pragma unroll
    for (int n = 0; n < 16; n++)
        #pragma unroll
        for (int q = 0; q < 4; q++) o[n][q] = 0.0f;

    const int g = lane >> 2, t = lane & 3;
    const uint32_t qaddr = sb + (wid * 16 + (lane & 15)) * ASTR + (lane >> 4) * 16;
    const uint32_t kvlane = (uint32_t)((lane & 15) * ASTR + (lane >> 4) * 16);

    for (int kb = 0; kb < nkb; kb++) {
        cp_wait<1>();
        __syncthreads();

        const int slot = kb & 1;
        const uint32_t kB = sb + QTILE + slot * KVSTAGE;
        const uint32_t vB = kB + KVTILE;
        const bool skip = (kb * 64 > q0w + 15);

        if (!skip) {
            float s[8][4];
            #pragma unroll
            for (int j = 0; j < 8; j++)
                #pragma unroll
                for (int q = 0; q < 4; q++) s[j][q] = 0.0f;

            #pragma unroll
            for (int ks = 0; ks < 8; ks++) {
                uint32_t ah4[4];
                ldsm4(ah4, qaddr + ks * 32);
                #pragma unroll
                for (int p2 = 0; p2 < 4; p2++) {
                    uint32_t bh4[4];
                    ldsm4(bh4, kB + kvlane + p2 * (16 * ASTR) + ks * 32);
                    #pragma unroll
                    for (int sl = 0; sl < 2; sl++)
                        mma16816(s[p2 * 2 + sl], ah4, bh4[sl], bh4[sl + 2]);
                }
            }

            const bool dm = (kb * 64 + 63 > q0w);
            const int r0 = q0w + g, r1 = q0w + 8 + g;
            float mx0 = -1e30f, mx1 = -1e30f;
            #pragma unroll
            for (int j = 0; j < 8; j++) {
                const int col = kb * 64 + 8 * j + 2 * t;
                float v0 = s[j][0] * qs, v1 = s[j][1] * qs;
                float v2 = s[j][2] * qs, v3 = s[j][3] * qs;
                if (dm) {
                    if (col     > r0) v0 = -1e30f;
                    if (col + 1 > r0) v1 = -1e30f;
                    if (col     > r1) v2 = -1e30f;
                    if (col + 1 > r1) v3 = -1e30f;
                }
                s[j][0] = v0; s[j][1] = v1; s[j][2] = v2; s[j][3] = v3;
                mx0 = fmaxf(mx0, fmaxf(v0, v1));
                mx1 = fmaxf(mx1, fmaxf(v2, v3));
            }
            mx0 = fmaxf(mx0, __shfl_xor_sync(0xffffffffu, mx0, 1));
            mx0 = fmaxf(mx0, __shfl_xor_sync(0xffffffffu, mx0, 2));
            mx1 = fmaxf(mx1, __shfl_xor_sync(0xffffffffu, mx1, 1));
            mx1 = fmaxf(mx1, __shfl_xor_sync(0xffffffffu, mx1, 2));

            const float mn0 = fmaxf(m[0], mx0);
            const float mn1 = fmaxf(m[1], mx1);
            float rs0 = 0.0f, rs1 = 0.0f;
            #pragma unroll
            for (int j = 0; j < 8; j++) {
                s[j][0] = exp2f(s[j][0] - mn0);
                s[j][1] = exp2f(s[j][1] - mn0);
                s[j][2] = exp2f(s[j][2] - mn1);
                s[j][3] = exp2f(s[j][3] - mn1);
                rs0 += s[j][0] + s[j][1];
                rs1 += s[j][2] + s[j][3];
            }
            rs0 += __shfl_xor_sync(0xffffffffu, rs0, 1);
            rs0 += __shfl_xor_sync(0xffffffffu, rs0, 2);
            rs1 += __shfl_xor_sync(0xffffffffu, rs1, 1);
            rs1 += __shfl_xor_sync(0xffffffffu, rs1, 2);

            const float f0 = exp2f(m[0] - mn0);
            const float f1 = exp2f(m[1] - mn1);
            l[0] = l[0] * f0 + rs0; l[1] = l[1] * f1 + rs1;
            m[0] = mn0; m[1] = mn1;
            #pragma unroll
            for (int n = 0; n < 16; n++) {
                o[n][0] *= f0; o[n][1] *= f0;
                o[n][2] *= f1; o[n][3] *= f1;
            }

            #pragma unroll
            for (int jp = 0; jp < 4; jp++) {
                uint32_t ph[4];
                {
                    const float* p0 = s[2 * jp];
                    const float* p1 = s[2 * jp + 1];
                    ph[0] = pack_h2(p0[0], p0[1]);
                    ph[1] = pack_h2(p0[2], p0[3]);
                    ph[2] = pack_h2(p1[0], p1[1]);
                    ph[3] = pack_h2(p1[2], p1[3]);
                }
                #pragma unroll
                for (int np = 0; np < 8; np++) {
                    uint32_t bh4[4];
                    ldsm4t(bh4, vB + kvlane + jp * (16 * ASTR) + np * 32);
                    mma16816(o[2 * np],     ph, bh4[0], bh4[1]);
                    mma16816(o[2 * np + 1], ph, bh4[2], bh4[3]);
                }
            }
        }

        __syncthreads();
        if (kb + 2 < nkb) issueKV(kb + 2, slot);
        cp_commit();
    }

    const float inv0 = 1.0f / l[0];
    const float inv1 = 1.0f / l[1];
    const int r0 = q0w + g, r1 = q0w + 8 + g;
    #pragma unroll
    for (int n = 0; n < 16; n++) {
        const int col = h * HD + n * 8 + 2 * t;
        *(__half2*)(ctxh + (size_t)r0 * EM + col) =
            __floats2half2_rn(o[n][0] * inv0, o[n][1] * inv0);
        *(__half2*)(ctxh + (size_t)r1 * EM + col) =
            __floats2half2_rn(o[n][2] * inv1, o[n][3] * inv1);
    }
}

// =====================================================================
extern "C" void kernel_launch(void* const* d_in, const int* in_sizes, int n_in,
                              void* d_out, int out_size)
{
    (void)in_sizes; (void)n_in; (void)out_size;
    const float* hs   = (const float*)d_in[0];
    const float* wqkv = (const float*)d_in[1];
    const float* bqkv = (const float*)d_in[2];
    const float* wo   = (const float*)d_in[3];
    const float* bo   = (const float*)d_in[4];
    float* out = (float*)d_out;

    __half *qkvh, *ah, *bh;
    cudaGetSymbolAddress((void**)&qkvh, g_qkvh);
    cudaGetSymbolAddress((void**)&ah, g_ah);
    cudaGetSymbolAddress((void**)&bh, g_bh);

    cudaFuncSetAttribute(gemm_mma, cudaFuncAttributeMaxDynamicSharedMemorySize, GEMM_SMEM);
    cudaFuncSetAttribute(flash_attn_mma, cudaFuncAttributeMaxDynamicSharedMemorySize, FLASH_SMEM);

    // 1) convert inputs to fp16
    conv_f16<<<(SQ * EM / 16 + 255) / 256, 256>>>(hs, ah, SQ * EM);
    conv_f16<<<(QKVC * EM / 16 + 255) / 256, 256>>>(wqkv, bh, QKVC * EM);

    // 2) QKV projection -> fp16
    dim3 g1(QKVC / 128, SQ / 64);
    gemm_mma<<<g1, 256, GEMM_SMEM>>>(ah, bh, bqkv, nullptr, qkvh, 1, QKVC, EM);

    // 3) convert Wo (stream-ordered after gemm1's reads of bh)
    conv_f16<<<(EM * EM / 16 + 255) / 256, 256>>>(wo, bh, EM * EM);

    // 4) causal flash attention -> ctx fp16 (overwrites ah)
    flash_attn_mma<<<(SQ / 128) * NH, 256, FLASH_SMEM>>>(qkvh, ah);

    // 5) output projection -> fp32 out
    dim3 g3(EM / 128, SQ / 64);
    gemm_mma<<<g3, 256, GEMM_SMEM>>>(ah, bh, bo, out, nullptr, 0, EM, EM);
}